// round 7
// baseline (speedup 1.0000x reference)
#include <cuda_runtime.h>
#include <cstdint>

// ---------------------------------------------------------------------------
// GumbelVectorQuantizer forward, GB300.
// B=8, T=2048, D=1024, V=16, K=512, d=64.
// ---------------------------------------------------------------------------

#define BB   8
#define TT   2048
#define DD   1024
#define VV   16
#define KK   512
#define DG   64
#define MROWS (BB * TT)          // 16384

#define OUT_QUANT   0
#define OUT_TARGETS (MROWS * DD)            // 16777216
#define OUT_LOSS    (MROWS * DD + MROWS)    // 16793600

// Scratch (device globals: allocation-free contract)
__device__ float g_Q[MROWS * DD];        // q = features @ Wq^T + bq
__device__ float g_P[VV * KK * DD];      // P[v][k][:] = codebooks[v][k] @ Wout_v^T (+bout at v=0)
__device__ float g_Wh[DD * DD];          // Wq tf32 hi part
__device__ float g_Wl[DD * DD];          // Wq tf32 lo part
__device__ int   g_idx[MROWS * VV];      // argmax indices
__device__ int   g_counts[VV * KK];      // codebook usage counts
__device__ float g_delta[VV];            // per-group safe score window

// ===========================================================================
// Helpers
// ===========================================================================
__device__ __forceinline__ uint32_t smem_to_u32(const void* p) {
    uint32_t a;
    asm("{ .reg .u64 t; cvta.to.shared.u64 t, %1; cvt.u32.u64 %0, t; }"
        : "=r"(a) : "l"(p));
    return a;
}
__device__ __forceinline__ void cp16(uint32_t dst, const void* src) {
    asm volatile("cp.async.cg.shared.global [%0], [%1], 16;"
                 :: "r"(dst), "l"(src) : "memory");
}
#define CP_COMMIT() asm volatile("cp.async.commit_group;" ::: "memory")
#define CP_WAIT1()  asm volatile("cp.async.wait_group 1;" ::: "memory")
#define CP_WAIT0()  asm volatile("cp.async.wait_group 0;" ::: "memory")

__device__ __forceinline__ uint32_t tf32_hi(float a) {
    float r;
    asm("cvt.rna.tf32.f32 %0, %1;" : "=f"(r) : "f"(a));
    return __float_as_uint(r);
}

__device__ __forceinline__ void mma_tf32(float* c, const uint32_t* a,
                                         uint32_t b0, uint32_t b1) {
    asm volatile(
        "mma.sync.aligned.m16n8k8.row.col.f32.tf32.tf32.f32 "
        "{%0,%1,%2,%3}, {%4,%5,%6,%7}, {%8,%9}, {%0,%1,%2,%3};"
        : "+f"(c[0]), "+f"(c[1]), "+f"(c[2]), "+f"(c[3])
        : "r"(a[0]), "r"(a[1]), "r"(a[2]), "r"(a[3]), "r"(b0), "r"(b1));
}

// ===========================================================================
// wsplit: Wh = tf32(W), Wl = tf32(W - Wh)
// ===========================================================================
__global__ __launch_bounds__(256)
void wsplit_k(const float* __restrict__ W, float* __restrict__ Wh,
              float* __restrict__ Wl) {
    const int i = blockIdx.x * 256 + threadIdx.x;   // float4 index
    float4 w = ((const float4*)W)[i];
    float4 h, l;
    h.x = __uint_as_float(tf32_hi(w.x)); l.x = __uint_as_float(tf32_hi(w.x - h.x));
    h.y = __uint_as_float(tf32_hi(w.y)); l.y = __uint_as_float(tf32_hi(w.y - h.y));
    h.z = __uint_as_float(tf32_hi(w.z)); l.z = __uint_as_float(tf32_hi(w.z - h.z));
    h.w = __uint_as_float(tf32_hi(w.w)); l.w = __uint_as_float(tf32_hi(w.w - h.w));
    ((float4*)Wh)[i] = h;
    ((float4*)Wl)[i] = l;
}

// ===========================================================================
// 3xTF32 tensor-core GEMM: C[M][1024] = A[M][1024] @ W[1024][1024]^T + bias
// 512 threads / 16 warps, 128x128 tile, 32x32 warp tile, BK=32.
// W pre-split into (Wh, Wl); A split in-register in the consumer.
// stage: A raw 16KB + Bh 16KB + Bl 16KB = 48KB, double-buffered = 96KB.
// ===========================================================================
#define G2_STAGE_B 49152
#define G2_BYTES   (2 * G2_STAGE_B)   // 98304

__global__ __launch_bounds__(512)
void gemm_mma3(const float* __restrict__ A, const float* __restrict__ Wh,
               const float* __restrict__ Wl, const float* __restrict__ bias,
               float* __restrict__ C) {
    extern __shared__ float smemf[];
    const int tid = threadIdx.x;
    const int lane = tid & 31;
    const int wid = tid >> 5;
    const int m0 = blockIdx.y * 128;
    const int n0 = blockIdx.x * 128;
    const uint32_t sb = smem_to_u32(smemf);

    // loader: thread -> (row, two float4 cols qp, qp+1) of the 128x32 chunk
    const int lrow = tid >> 2;            // 0..127
    const int qp   = (tid & 3) * 2;       // 0,2,4,6
    const uint32_t s0 = (uint32_t)(lrow * 8 + (qp ^ (lrow & 7))) * 16u;
    const uint32_t s1 = (uint32_t)(lrow * 8 + ((qp + 1) ^ (lrow & 7))) * 16u;
    const float* Ag  = A  + (size_t)(m0 + lrow) * DD + qp * 4;
    const float* Bhg = Wh + (size_t)(n0 + lrow) * DD + qp * 4;
    const float* Blg = Wl + (size_t)(n0 + lrow) * DD + qp * 4;

    const int gr = lane >> 2;   // 0..7
    const int gc = lane & 3;    // 0..3
    const int m0w = (wid & 3) * 32;
    const int n0w = (wid >> 2) * 32;

    float acc[2][4][4];
#pragma unroll
    for (int mi = 0; mi < 2; mi++)
#pragma unroll
        for (int ni = 0; ni < 4; ni++)
#pragma unroll
            for (int r = 0; r < 4; r++) acc[mi][ni][r] = 0.0f;

    // prologue: chunk 0 into stage 0
    cp16(sb + s0, Ag);
    cp16(sb + s1, Ag + 4);
    cp16(sb + 16384 + s0, Bhg);
    cp16(sb + 16384 + s1, Bhg + 4);
    cp16(sb + 32768 + s0, Blg);
    cp16(sb + 32768 + s1, Blg + 4);
    CP_COMMIT();

    for (int i = 0; i < 32; i++) {
        const int s = i & 1;
        if (i < 31) {
            const uint32_t st = sb + (s ^ 1) * G2_STAGE_B;
            const int ko = (i + 1) * 32;
            cp16(st + s0, Ag + ko);
            cp16(st + s1, Ag + ko + 4);
            cp16(st + 16384 + s0, Bhg + ko);
            cp16(st + 16384 + s1, Bhg + ko + 4);
            cp16(st + 32768 + s0, Blg + ko);
            cp16(st + 32768 + s1, Blg + ko + 4);
            CP_COMMIT();
            CP_WAIT1();
        } else {
            CP_WAIT0();
        }
        __syncthreads();

        const float* As  = smemf + s * (G2_STAGE_B / 4);
        const float* Bhs = As + 4096;
        const float* Bls = As + 8192;
#pragma unroll
        for (int kk = 0; kk < 32; kk += 8) {
            const int swz = gr * 4;
            const int c0 = (kk + gc) ^ swz;
            const int c1 = (kk + gc + 4) ^ swz;
            uint32_t bh[4][2], bl[4][2];
#pragma unroll
            for (int ni = 0; ni < 4; ni++) {
                const int n = n0w + ni * 8 + gr;
                bh[ni][0] = __float_as_uint(Bhs[n * 32 + c0]);
                bh[ni][1] = __float_as_uint(Bhs[n * 32 + c1]);
                bl[ni][0] = __float_as_uint(Bls[n * 32 + c0]);
                bl[ni][1] = __float_as_uint(Bls[n * 32 + c1]);
            }
#pragma unroll
            for (int mi = 0; mi < 2; mi++) {
                const int r0 = m0w + mi * 16 + gr;
                float a0 = As[r0 * 32 + c0];
                float a1 = As[(r0 + 8) * 32 + c0];
                float a2 = As[r0 * 32 + c1];
                float a3 = As[(r0 + 8) * 32 + c1];
                uint32_t ah[4], al[4];
                ah[0] = tf32_hi(a0); ah[1] = tf32_hi(a1);
                ah[2] = tf32_hi(a2); ah[3] = tf32_hi(a3);
                al[0] = tf32_hi(a0 - __uint_as_float(ah[0]));
                al[1] = tf32_hi(a1 - __uint_as_float(ah[1]));
                al[2] = tf32_hi(a2 - __uint_as_float(ah[2]));
                al[3] = tf32_hi(a3 - __uint_as_float(ah[3]));
#pragma unroll
                for (int ni = 0; ni < 4; ni++) {
                    mma_tf32(acc[mi][ni], ah, bh[ni][0], bh[ni][1]);
                    mma_tf32(acc[mi][ni], ah, bl[ni][0], bl[ni][1]);
                    mma_tf32(acc[mi][ni], al, bh[ni][0], bh[ni][1]);
                }
            }
        }
        __syncthreads();
    }

#pragma unroll
    for (int mi = 0; mi < 2; mi++) {
#pragma unroll
        for (int ni = 0; ni < 4; ni++) {
            const int row = m0 + m0w + mi * 16 + gr;
            const int col = n0 + n0w + ni * 8 + gc * 2;
            const float bx = bias[col], by = bias[col + 1];
            float2 v0 = make_float2(acc[mi][ni][0] + bx, acc[mi][ni][1] + by);
            float2 v1 = make_float2(acc[mi][ni][2] + bx, acc[mi][ni][3] + by);
            *(float2*)(C + (size_t)row * DD + col) = v0;
            *(float2*)(C + (size_t)(row + 8) * DD + col) = v1;
        }
    }
}

// ===========================================================================
// pmat: P[v][k][n] = sum_d codebooks[v][k][d] * Wout[n][v*64+d]  (+bout[n] @ v==0)
// ===========================================================================
__global__ __launch_bounds__(256)
void pmat_k(const float* __restrict__ cbk, const float* __restrict__ Wout,
            const float* __restrict__ bout, float* __restrict__ P) {
    __shared__ float Ct[64][65];
    __shared__ float Wt[128][65];
    const int v = blockIdx.z;
    const int k0 = blockIdx.y * 64;
    const int n0 = blockIdx.x * 128;
    const int tid = threadIdx.x;

    for (int i = tid; i < 64 * 16; i += 256) {
        int rr = i >> 4, dq = (i & 15) * 4;
        float4 c = *(const float4*)(cbk + (((size_t)v * KK + k0 + rr) << 6) + dq);
        Ct[rr][dq + 0] = c.x; Ct[rr][dq + 1] = c.y;
        Ct[rr][dq + 2] = c.z; Ct[rr][dq + 3] = c.w;
    }
    for (int i = tid; i < 128 * 16; i += 256) {
        int rr = i >> 4, dq = (i & 15) * 4;
        float4 wv = *(const float4*)(Wout + (size_t)(n0 + rr) * DD + v * DG + dq);
        Wt[rr][dq + 0] = wv.x; Wt[rr][dq + 1] = wv.y;
        Wt[rr][dq + 2] = wv.z; Wt[rr][dq + 3] = wv.w;
    }
    __syncthreads();

    const int ks = (tid >> 4) * 4;
    const int ns = (tid & 15) * 8;
    float acc[4][8];
#pragma unroll
    for (int i = 0; i < 4; i++)
#pragma unroll
        for (int j = 0; j < 8; j++) acc[i][j] = 0.0f;

#pragma unroll 8
    for (int d = 0; d < 64; d++) {
        float cv[4], wv[8];
#pragma unroll
        for (int i = 0; i < 4; i++) cv[i] = Ct[ks + i][d];
#pragma unroll
        for (int j = 0; j < 8; j++) wv[j] = Wt[ns + j][d];
#pragma unroll
        for (int i = 0; i < 4; i++)
#pragma unroll
            for (int j = 0; j < 8; j++)
                acc[i][j] = fmaf(cv[i], wv[j], acc[i][j]);
    }

#pragma unroll
    for (int i = 0; i < 4; i++) {
        float* prow = P + (((size_t)v * KK + k0 + ks + i) << 10) + n0 + ns;
        float4 o0, o1;
        float b0 = 0, b1 = 0, b2 = 0, b3 = 0, b4 = 0, b5 = 0, b6 = 0, b7 = 0;
        if (v == 0) {
            b0 = bout[n0 + ns + 0]; b1 = bout[n0 + ns + 1];
            b2 = bout[n0 + ns + 2]; b3 = bout[n0 + ns + 3];
            b4 = bout[n0 + ns + 4]; b5 = bout[n0 + ns + 5];
            b6 = bout[n0 + ns + 6]; b7 = bout[n0 + ns + 7];
        }
        o0.x = acc[i][0] + b0; o0.y = acc[i][1] + b1;
        o0.z = acc[i][2] + b2; o0.w = acc[i][3] + b3;
        o1.x = acc[i][4] + b4; o1.y = acc[i][5] + b5;
        o1.z = acc[i][6] + b6; o1.w = acc[i][7] + b7;
        *(float4*)(prow + 0) = o0;
        *(float4*)(prow + 4) = o1;
    }
}

// ---------------------------------------------------------------------------
// Threefry2x32, JAX partitionable path, key = (0, 42).
// ---------------------------------------------------------------------------
__device__ __forceinline__ uint32_t rotl32(uint32_t x, int r) {
    return __funnelshift_l(x, x, r);
}
__device__ __forceinline__ void tf_round(uint32_t& x0, uint32_t& x1, int r) {
    x0 += x1;
    x1 = rotl32(x1, r);
    x1 ^= x0;
}
__device__ __forceinline__ uint32_t tf_bits(uint32_t i) {
    const uint32_t ks0 = 0u;
    const uint32_t ks1 = 42u;
    const uint32_t ks2 = 0x1BD11BDAu ^ ks0 ^ ks1;
    uint32_t x0 = 0u + ks0;
    uint32_t x1 = i + ks1;
    tf_round(x0, x1, 13); tf_round(x0, x1, 15); tf_round(x0, x1, 26); tf_round(x0, x1, 6);
    x0 += ks1; x1 += ks2 + 1u;
    tf_round(x0, x1, 17); tf_round(x0, x1, 29); tf_round(x0, x1, 16); tf_round(x0, x1, 24);
    x0 += ks2; x1 += ks0 + 2u;
    tf_round(x0, x1, 13); tf_round(x0, x1, 15); tf_round(x0, x1, 26); tf_round(x0, x1, 6);
    x0 += ks0; x1 += ks1 + 3u;
    tf_round(x0, x1, 17); tf_round(x0, x1, 29); tf_round(x0, x1, 16); tf_round(x0, x1, 24);
    x0 += ks1; x1 += ks2 + 4u;
    tf_round(x0, x1, 13); tf_round(x0, x1, 15); tf_round(x0, x1, 26); tf_round(x0, x1, 6);
    x0 += ks2; x1 += ks0 + 5u;
    return x0 ^ x1;
}

__device__ __forceinline__ float gumbel_from_ubits(uint32_t ub) {
    float u = __uint_as_float(0x3f800000u | ub) - 1.0f;
    return -logf(-logf(u + 1e-8f) + 1e-8f);
}

// ---------------------------------------------------------------------------
// delta_k: per-v safe window  Delta_v = 2*max_k ||c_k|| + margin
// ---------------------------------------------------------------------------
__global__ void delta_k(const float* __restrict__ cbk, float* __restrict__ gd) {
    __shared__ float red[16];
    const int v = blockIdx.x;
    const int k = threadIdx.x;
    const int lane = k & 31, w = k >> 5;
    const float* crow = cbk + ((size_t)(v * KK + k)) * DG;
    float s = 0.0f;
#pragma unroll
    for (int d = 0; d < DG; d += 4) {
        float4 c = *(const float4*)(crow + d);
        s += c.x * c.x + c.y * c.y + c.z * c.z + c.w * c.w;
    }
#pragma unroll
    for (int o = 16; o; o >>= 1) s = fmaxf(s, __shfl_xor_sync(0xffffffffu, s, o));
    if (lane == 0) red[w] = s;
    __syncthreads();
    if (k == 0) {
        float m = 0.0f;
#pragma unroll
        for (int i = 0; i < 16; i++) m = fmaxf(m, red[i]);
        gd[v] = 2.0f * sqrtf(m) + 0.05f;
    }
}

// ---------------------------------------------------------------------------
// fused_vq2: one warp per (b,t,v) group. No shared, no block syncs.
// ---------------------------------------------------------------------------
__global__ __launch_bounds__(256)
void fused_vq2(const float* __restrict__ Q, const float* __restrict__ cbk,
               const float* __restrict__ gdelta,
               int* __restrict__ idxOut, int* __restrict__ counts) {
    const int v = blockIdx.x >> 11;
    const int t = blockIdx.x & 2047;
    const int b = threadIdx.x >> 5;
    const int lane = threadIdx.x & 31;

    const uint32_t base = (uint32_t)t * 8192u + (uint32_t)v * 512u +
                          ((uint32_t)b << 24) + (uint32_t)lane;
    uint32_t r[16];
    uint32_t m = 0u;
#pragma unroll
    for (int j = 0; j < 16; j++) {
        r[j] = tf_bits(base + 32u * j);
        m = max(m, r[j]);
    }
#pragma unroll
    for (int o = 16; o; o >>= 1) m = max(m, __shfl_xor_sync(0xffffffffu, m, o));

    const float gmax = gumbel_from_ubits(m >> 9);
    const float glo = gmax - gdelta[v];
    const float ulo = expf(-(expf(-glo) - 1e-8f)) - 1e-8f;
    const int it = (int)floorf(ulo * 8388608.0f) - 16;
    const uint32_t thr = ((uint32_t)max(it, 0)) << 9;

    const float* qrow = Q + ((size_t)(b * TT + t)) * DD + v * DG;
    const float q0 = qrow[lane], q1 = qrow[lane + 32];
    float q2 = q0 * q0 + q1 * q1;
#pragma unroll
    for (int o = 16; o; o >>= 1) q2 += __shfl_xor_sync(0xffffffffu, q2, o);

    float bestS = -3.4e38f;
    int bestK = 0;
#pragma unroll
    for (int j = 0; j < 16; j++) {
        unsigned mask = __ballot_sync(0xffffffffu, r[j] >= thr);
        while (mask) {
            const int src = __ffs(mask) - 1;
            mask &= mask - 1;
            const int kc = 32 * j + src;
            const uint32_t ubc = __shfl_sync(0xffffffffu, r[j], src) >> 9;
            const float* crow = cbk + (((size_t)v * KK + kc) << 6);
            const float c0 = crow[lane], c1 = crow[lane + 32];
            float qc = q0 * c0 + q1 * c1;
            float c2 = c0 * c0 + c1 * c1;
#pragma unroll
            for (int o = 16; o; o >>= 1) {
                qc += __shfl_xor_sync(0xffffffffu, qc, o);
                c2 += __shfl_xor_sync(0xffffffffu, c2, o);
            }
            const float dist = sqrtf(fmaxf(q2 + c2 - 2.0f * qc, 0.0f));
            const float s = gumbel_from_ubits(ubc) - dist;
            if (s > bestS) { bestS = s; bestK = kc; }
        }
    }

    if (lane == 0) {
        idxOut[(b * TT + t) * VV + v] = bestK;
        atomicAdd(&counts[v * KK + bestK], 1);
    }
}

// ---------------------------------------------------------------------------
// gather_sum: quantized[b,t] = sum_v P[v][idx_v]; also emits targets.
// ---------------------------------------------------------------------------
__global__ __launch_bounds__(128)
void gather_sum(const float* __restrict__ P, const int* __restrict__ idx,
                float* __restrict__ out) {
    __shared__ int sidx[VV];
    const int row = blockIdx.x;
    const int tid = threadIdx.x;
    if (tid < VV) sidx[tid] = idx[row * VV + tid];
    __syncthreads();

    const int n = tid * 8;
    float4 a0 = make_float4(0.f, 0.f, 0.f, 0.f);
    float4 a1 = make_float4(0.f, 0.f, 0.f, 0.f);
#pragma unroll
    for (int v = 0; v < VV; v++) {
        const float* p = P + ((((size_t)v << 9) + sidx[v]) << 10) + n;
        float4 x = *(const float4*)(p + 0);
        float4 y = *(const float4*)(p + 4);
        a0.x += x.x; a0.y += x.y; a0.z += x.z; a0.w += x.w;
        a1.x += y.x; a1.y += y.y; a1.z += y.z; a1.w += y.w;
    }
    float* o = out + (size_t)row * DD + n;
    *(float4*)(o + 0) = a0;
    *(float4*)(o + 4) = a1;

    if (tid == 0) {
        int s = 0;
#pragma unroll
        for (int v = 0; v < VV; v++) s += sidx[v] * (v * KK);
        out[OUT_TARGETS + row] = (float)s;
    }
}

// ---------------------------------------------------------------------------
// Small kernels
// ---------------------------------------------------------------------------
__global__ void zero_counts_k(int* __restrict__ counts) {
    int i = blockIdx.x * blockDim.x + threadIdx.x;
    if (i < VV * KK) counts[i] = 0;
}

__global__ void loss_k(const int* __restrict__ counts, float* __restrict__ out) {
    __shared__ float ent_s[VV];
    const int tid = threadIdx.x, lane = tid & 31, w = tid >> 5;
    if (w < VV) {
        float tot = 0.0f;
        for (int kk = lane; kk < KK; kk += 32) tot += (float)counts[w * KK + kk];
#pragma unroll
        for (int o = 16; o; o >>= 1) tot += __shfl_xor_sync(0xffffffffu, tot, o);
        float inv = 1.0f / tot;
        float pl = 0.0f;
        for (int kk = lane; kk < KK; kk += 32) {
            float p = (float)counts[w * KK + kk] * inv;
            pl += p * logf(p + 1e-8f);
        }
#pragma unroll
        for (int o = 16; o; o >>= 1) pl += __shfl_xor_sync(0xffffffffu, pl, o);
        if (lane == 0) ent_s[w] = -pl;
    }
    __syncthreads();
    if (tid == 0) {
        float lk = logf(512.0f);
        float acc = 0.0f;
#pragma unroll
        for (int v = 0; v < VV; v++) acc += ent_s[v] / lk;
        float diversity = -(acc / (float)VV);
        out[OUT_LOSS] = 0.1f * diversity;
    }
}

// ---------------------------------------------------------------------------
// Launch
// ---------------------------------------------------------------------------
extern "C" void kernel_launch(void* const* d_in, const int* in_sizes, int n_in,
                              void* d_out, int out_size) {
    const float* features  = (const float*)d_in[0];
    const float* codebooks = (const float*)d_in[1];
    const float* Wq        = (const float*)d_in[2];
    const float* bq        = (const float*)d_in[3];
    const float* Wout      = (const float*)d_in[4];
    const float* bout      = (const float*)d_in[5];
    float* out = (float*)d_out;

    float* Qb;  cudaGetSymbolAddress((void**)&Qb,  g_Q);
    float* Pb;  cudaGetSymbolAddress((void**)&Pb,  g_P);
    float* WhP; cudaGetSymbolAddress((void**)&WhP, g_Wh);
    float* WlP; cudaGetSymbolAddress((void**)&WlP, g_Wl);
    int* idxP;  cudaGetSymbolAddress((void**)&idxP, g_idx);
    int* cntP;  cudaGetSymbolAddress((void**)&cntP, g_counts);
    float* dP;  cudaGetSymbolAddress((void**)&dP,  g_delta);

    cudaFuncSetAttribute(gemm_mma3,
                         cudaFuncAttributeMaxDynamicSharedMemorySize, G2_BYTES);

    zero_counts_k<<<16, 512>>>(cntP);
    wsplit_k<<<DD * DD / 1024, 256>>>(Wq, WhP, WlP);
    delta_k<<<VV, 512>>>(codebooks, dP);
    pmat_k<<<dim3(8, 8, VV), 256>>>(codebooks, Wout, bout, Pb);
    gemm_mma3<<<dim3(8, 128), 512, G2_BYTES>>>(features, WhP, WlP, bq, Qb);
    fused_vq2<<<VV * TT, 256>>>(Qb, codebooks, dP, idxP, cntP);
    gather_sum<<<MROWS, 128>>>(Pb, idxP, out);
    loss_k<<<1, 512>>>(cntP, out);
}

// round 8
// speedup vs baseline: 1.0901x; 1.0901x over previous
#include <cuda_runtime.h>
#include <cstdint>

// ---------------------------------------------------------------------------
// GumbelVectorQuantizer forward, GB300.
// B=8, T=2048, D=1024, V=16, K=512, d=64.
// ---------------------------------------------------------------------------

#define BB   8
#define TT   2048
#define DD   1024
#define VV   16
#define KK   512
#define DG   64
#define MROWS (BB * TT)          // 16384
#define NGRP  (MROWS * VV)       // 262144

#define OUT_QUANT   0
#define OUT_TARGETS (MROWS * DD)            // 16777216
#define OUT_LOSS    (MROWS * DD + MROWS)    // 16793600

// Scratch (device globals: allocation-free contract)
__device__ float    g_Q[MROWS * DD];     // q = features @ Wq^T + bq
__device__ float    g_P[VV * KK * DD];   // P[v][k][:] = codebooks[v][k] @ Wout_v^T (+bout at v=0)
__device__ float    g_Wh[DD * DD];       // Wq tf32 hi part
__device__ float    g_Wl[DD * DD];       // Wq tf32 lo part
__device__ int      g_idx[NGRP];         // final argmax idx, or -(numcands) marker
__device__ uint32_t g_cand[NGRP * 8];    // packed (ubits<<9)|k per candidate
__device__ int      g_counts[VV * KK];   // codebook usage counts
__device__ float    g_delta[VV];         // per-group safe score window

// ===========================================================================
// Helpers
// ===========================================================================
__device__ __forceinline__ uint32_t smem_to_u32(const void* p) {
    uint32_t a;
    asm("{ .reg .u64 t; cvta.to.shared.u64 t, %1; cvt.u32.u64 %0, t; }"
        : "=r"(a) : "l"(p));
    return a;
}
__device__ __forceinline__ void cp16(uint32_t dst, const void* src) {
    asm volatile("cp.async.cg.shared.global [%0], [%1], 16;"
                 :: "r"(dst), "l"(src) : "memory");
}
#define CP_COMMIT() asm volatile("cp.async.commit_group;" ::: "memory")
#define CP_WAIT1()  asm volatile("cp.async.wait_group 1;" ::: "memory")
#define CP_WAIT0()  asm volatile("cp.async.wait_group 0;" ::: "memory")

__device__ __forceinline__ uint32_t tf32_hi(float a) {
    float r;
    asm("cvt.rna.tf32.f32 %0, %1;" : "=f"(r) : "f"(a));
    return __float_as_uint(r);
}

__device__ __forceinline__ void mma_tf32(float* c, const uint32_t* a,
                                         uint32_t b0, uint32_t b1) {
    asm volatile(
        "mma.sync.aligned.m16n8k8.row.col.f32.tf32.tf32.f32 "
        "{%0,%1,%2,%3}, {%4,%5,%6,%7}, {%8,%9}, {%0,%1,%2,%3};"
        : "+f"(c[0]), "+f"(c[1]), "+f"(c[2]), "+f"(c[3])
        : "r"(a[0]), "r"(a[1]), "r"(a[2]), "r"(a[3]), "r"(b0), "r"(b1));
}

// ===========================================================================
// wsplit: Wh = tf32(W), Wl = tf32(W - Wh)
// ===========================================================================
__global__ __launch_bounds__(256)
void wsplit_k(const float* __restrict__ W, float* __restrict__ Wh,
              float* __restrict__ Wl) {
    const int i = blockIdx.x * 256 + threadIdx.x;   // float4 index
    float4 w = ((const float4*)W)[i];
    float4 h, l;
    h.x = __uint_as_float(tf32_hi(w.x)); l.x = __uint_as_float(tf32_hi(w.x - h.x));
    h.y = __uint_as_float(tf32_hi(w.y)); l.y = __uint_as_float(tf32_hi(w.y - h.y));
    h.z = __uint_as_float(tf32_hi(w.z)); l.z = __uint_as_float(tf32_hi(w.z - h.z));
    h.w = __uint_as_float(tf32_hi(w.w)); l.w = __uint_as_float(tf32_hi(w.w - h.w));
    ((float4*)Wh)[i] = h;
    ((float4*)Wl)[i] = l;
}

// ===========================================================================
// 3xTF32 tensor-core GEMM: C[M][1024] = A[M][1024] @ W[1024][1024]^T + bias
// 512 threads / 16 warps, 128x128 tile, 32x32 warp tile, BK=32.
// ===========================================================================
#define G2_STAGE_B 49152
#define G2_BYTES   (2 * G2_STAGE_B)   // 98304

__global__ __launch_bounds__(512)
void gemm_mma3(const float* __restrict__ A, const float* __restrict__ Wh,
               const float* __restrict__ Wl, const float* __restrict__ bias,
               float* __restrict__ C) {
    extern __shared__ float smemf[];
    const int tid = threadIdx.x;
    const int lane = tid & 31;
    const int wid = tid >> 5;
    const int m0 = blockIdx.y * 128;
    const int n0 = blockIdx.x * 128;
    const uint32_t sb = smem_to_u32(smemf);

    const int lrow = tid >> 2;            // 0..127
    const int qp   = (tid & 3) * 2;       // 0,2,4,6
    const uint32_t s0 = (uint32_t)(lrow * 8 + (qp ^ (lrow & 7))) * 16u;
    const uint32_t s1 = (uint32_t)(lrow * 8 + ((qp + 1) ^ (lrow & 7))) * 16u;
    const float* Ag  = A  + (size_t)(m0 + lrow) * DD + qp * 4;
    const float* Bhg = Wh + (size_t)(n0 + lrow) * DD + qp * 4;
    const float* Blg = Wl + (size_t)(n0 + lrow) * DD + qp * 4;

    const int gr = lane >> 2;
    const int gc = lane & 3;
    const int m0w = (wid & 3) * 32;
    const int n0w = (wid >> 2) * 32;

    float acc[2][4][4];
#pragma unroll
    for (int mi = 0; mi < 2; mi++)
#pragma unroll
        for (int ni = 0; ni < 4; ni++)
#pragma unroll
            for (int r = 0; r < 4; r++) acc[mi][ni][r] = 0.0f;

    cp16(sb + s0, Ag);
    cp16(sb + s1, Ag + 4);
    cp16(sb + 16384 + s0, Bhg);
    cp16(sb + 16384 + s1, Bhg + 4);
    cp16(sb + 32768 + s0, Blg);
    cp16(sb + 32768 + s1, Blg + 4);
    CP_COMMIT();

    for (int i = 0; i < 32; i++) {
        const int s = i & 1;
        if (i < 31) {
            const uint32_t st = sb + (s ^ 1) * G2_STAGE_B;
            const int ko = (i + 1) * 32;
            cp16(st + s0, Ag + ko);
            cp16(st + s1, Ag + ko + 4);
            cp16(st + 16384 + s0, Bhg + ko);
            cp16(st + 16384 + s1, Bhg + ko + 4);
            cp16(st + 32768 + s0, Blg + ko);
            cp16(st + 32768 + s1, Blg + ko + 4);
            CP_COMMIT();
            CP_WAIT1();
        } else {
            CP_WAIT0();
        }
        __syncthreads();

        const float* As  = smemf + s * (G2_STAGE_B / 4);
        const float* Bhs = As + 4096;
        const float* Bls = As + 8192;
#pragma unroll
        for (int kk = 0; kk < 32; kk += 8) {
            const int swz = gr * 4;
            const int c0 = (kk + gc) ^ swz;
            const int c1 = (kk + gc + 4) ^ swz;
            uint32_t bh[4][2], bl[4][2];
#pragma unroll
            for (int ni = 0; ni < 4; ni++) {
                const int n = n0w + ni * 8 + gr;
                bh[ni][0] = __float_as_uint(Bhs[n * 32 + c0]);
                bh[ni][1] = __float_as_uint(Bhs[n * 32 + c1]);
                bl[ni][0] = __float_as_uint(Bls[n * 32 + c0]);
                bl[ni][1] = __float_as_uint(Bls[n * 32 + c1]);
            }
#pragma unroll
            for (int mi = 0; mi < 2; mi++) {
                const int r0 = m0w + mi * 16 + gr;
                float a0 = As[r0 * 32 + c0];
                float a1 = As[(r0 + 8) * 32 + c0];
                float a2 = As[r0 * 32 + c1];
                float a3 = As[(r0 + 8) * 32 + c1];
                uint32_t ah[4], al[4];
                ah[0] = tf32_hi(a0); ah[1] = tf32_hi(a1);
                ah[2] = tf32_hi(a2); ah[3] = tf32_hi(a3);
                al[0] = tf32_hi(a0 - __uint_as_float(ah[0]));
                al[1] = tf32_hi(a1 - __uint_as_float(ah[1]));
                al[2] = tf32_hi(a2 - __uint_as_float(ah[2]));
                al[3] = tf32_hi(a3 - __uint_as_float(ah[3]));
#pragma unroll
                for (int ni = 0; ni < 4; ni++) {
                    mma_tf32(acc[mi][ni], ah, bh[ni][0], bh[ni][1]);
                    mma_tf32(acc[mi][ni], ah, bl[ni][0], bl[ni][1]);
                    mma_tf32(acc[mi][ni], al, bh[ni][0], bh[ni][1]);
                }
            }
        }
        __syncthreads();
    }

#pragma unroll
    for (int mi = 0; mi < 2; mi++) {
#pragma unroll
        for (int ni = 0; ni < 4; ni++) {
            const int row = m0 + m0w + mi * 16 + gr;
            const int col = n0 + n0w + ni * 8 + gc * 2;
            const float bx = bias[col], by = bias[col + 1];
            float2 v0 = make_float2(acc[mi][ni][0] + bx, acc[mi][ni][1] + by);
            float2 v1 = make_float2(acc[mi][ni][2] + bx, acc[mi][ni][3] + by);
            *(float2*)(C + (size_t)row * DD + col) = v0;
            *(float2*)(C + (size_t)(row + 8) * DD + col) = v1;
        }
    }
}

// ===========================================================================
// pmat: P[v][k][n] = sum_d codebooks[v][k][d] * Wout[n][v*64+d]  (+bout[n] @ v==0)
// ===========================================================================
__global__ __launch_bounds__(256)
void pmat_k(const float* __restrict__ cbk, const float* __restrict__ Wout,
            const float* __restrict__ bout, float* __restrict__ P) {
    __shared__ float Ct[64][65];
    __shared__ float Wt[128][65];
    const int v = blockIdx.z;
    const int k0 = blockIdx.y * 64;
    const int n0 = blockIdx.x * 128;
    const int tid = threadIdx.x;

    for (int i = tid; i < 64 * 16; i += 256) {
        int rr = i >> 4, dq = (i & 15) * 4;
        float4 c = *(const float4*)(cbk + (((size_t)v * KK + k0 + rr) << 6) + dq);
        Ct[rr][dq + 0] = c.x; Ct[rr][dq + 1] = c.y;
        Ct[rr][dq + 2] = c.z; Ct[rr][dq + 3] = c.w;
    }
    for (int i = tid; i < 128 * 16; i += 256) {
        int rr = i >> 4, dq = (i & 15) * 4;
        float4 wv = *(const float4*)(Wout + (size_t)(n0 + rr) * DD + v * DG + dq);
        Wt[rr][dq + 0] = wv.x; Wt[rr][dq + 1] = wv.y;
        Wt[rr][dq + 2] = wv.z; Wt[rr][dq + 3] = wv.w;
    }
    __syncthreads();

    const int ks = (tid >> 4) * 4;
    const int ns = (tid & 15) * 8;
    float acc[4][8];
#pragma unroll
    for (int i = 0; i < 4; i++)
#pragma unroll
        for (int j = 0; j < 8; j++) acc[i][j] = 0.0f;

#pragma unroll 8
    for (int d = 0; d < 64; d++) {
        float cv[4], wv[8];
#pragma unroll
        for (int i = 0; i < 4; i++) cv[i] = Ct[ks + i][d];
#pragma unroll
        for (int j = 0; j < 8; j++) wv[j] = Wt[ns + j][d];
#pragma unroll
        for (int i = 0; i < 4; i++)
#pragma unroll
            for (int j = 0; j < 8; j++)
                acc[i][j] = fmaf(cv[i], wv[j], acc[i][j]);
    }

#pragma unroll
    for (int i = 0; i < 4; i++) {
        float* prow = P + (((size_t)v * KK + k0 + ks + i) << 10) + n0 + ns;
        float4 o0, o1;
        float b0 = 0, b1 = 0, b2 = 0, b3 = 0, b4 = 0, b5 = 0, b6 = 0, b7 = 0;
        if (v == 0) {
            b0 = bout[n0 + ns + 0]; b1 = bout[n0 + ns + 1];
            b2 = bout[n0 + ns + 2]; b3 = bout[n0 + ns + 3];
            b4 = bout[n0 + ns + 4]; b5 = bout[n0 + ns + 5];
            b6 = bout[n0 + ns + 6]; b7 = bout[n0 + ns + 7];
        }
        o0.x = acc[i][0] + b0; o0.y = acc[i][1] + b1;
        o0.z = acc[i][2] + b2; o0.w = acc[i][3] + b3;
        o1.x = acc[i][4] + b4; o1.y = acc[i][5] + b5;
        o1.z = acc[i][6] + b6; o1.w = acc[i][7] + b7;
        *(float4*)(prow + 0) = o0;
        *(float4*)(prow + 4) = o1;
    }
}

// ---------------------------------------------------------------------------
// Threefry2x32, JAX partitionable path, key = (0, 42).
// ---------------------------------------------------------------------------
__device__ __forceinline__ uint32_t rotl32(uint32_t x, int r) {
    return __funnelshift_l(x, x, r);
}
__device__ __forceinline__ void tf_round(uint32_t& x0, uint32_t& x1, int r) {
    x0 += x1;
    x1 = rotl32(x1, r);
    x1 ^= x0;
}
__device__ __forceinline__ uint32_t tf_bits(uint32_t i) {
    const uint32_t ks0 = 0u;
    const uint32_t ks1 = 42u;
    const uint32_t ks2 = 0x1BD11BDAu ^ ks0 ^ ks1;
    uint32_t x0 = 0u + ks0;
    uint32_t x1 = i + ks1;
    tf_round(x0, x1, 13); tf_round(x0, x1, 15); tf_round(x0, x1, 26); tf_round(x0, x1, 6);
    x0 += ks1; x1 += ks2 + 1u;
    tf_round(x0, x1, 17); tf_round(x0, x1, 29); tf_round(x0, x1, 16); tf_round(x0, x1, 24);
    x0 += ks2; x1 += ks0 + 2u;
    tf_round(x0, x1, 13); tf_round(x0, x1, 15); tf_round(x0, x1, 26); tf_round(x0, x1, 6);
    x0 += ks0; x1 += ks1 + 3u;
    tf_round(x0, x1, 17); tf_round(x0, x1, 29); tf_round(x0, x1, 16); tf_round(x0, x1, 24);
    x0 += ks1; x1 += ks2 + 4u;
    tf_round(x0, x1, 13); tf_round(x0, x1, 15); tf_round(x0, x1, 26); tf_round(x0, x1, 6);
    x0 += ks2; x1 += ks0 + 5u;
    return x0 ^ x1;
}

__device__ __forceinline__ float gumbel_from_ubits(uint32_t ub) {
    float u = __uint_as_float(0x3f800000u | ub) - 1.0f;
    return -logf(-logf(u + 1e-8f) + 1e-8f);
}

// ---------------------------------------------------------------------------
// delta_k: per-v safe window  Delta_v = 2*max_k ||c_k|| + margin
// ---------------------------------------------------------------------------
__global__ void delta_k(const float* __restrict__ cbk, float* __restrict__ gd) {
    __shared__ float red[16];
    const int v = blockIdx.x;
    const int k = threadIdx.x;
    const int lane = k & 31, w = k >> 5;
    const float* crow = cbk + ((size_t)(v * KK + k)) * DG;
    float s = 0.0f;
#pragma unroll
    for (int d = 0; d < DG; d += 4) {
        float4 c = *(const float4*)(crow + d);
        s += c.x * c.x + c.y * c.y + c.z * c.z + c.w * c.w;
    }
#pragma unroll
    for (int o = 16; o; o >>= 1) s = fmaxf(s, __shfl_xor_sync(0xffffffffu, s, o));
    if (lane == 0) red[w] = s;
    __syncthreads();
    if (k == 0) {
        float m = 0.0f;
#pragma unroll
        for (int i = 0; i < 16; i++) m = fmaxf(m, red[i]);
        gd[v] = 2.0f * sqrtf(m) + 0.05f;
    }
}

// ---------------------------------------------------------------------------
// rng_k: threefry + integer max + threshold + candidate collection.
// NO dependency on Q — runs concurrently with the GEMM.
// Single-candidate groups finalize immediately; others store packed cands.
// ---------------------------------------------------------------------------
__global__ __launch_bounds__(256)
void rng_k(const float* __restrict__ gdelta, int* __restrict__ idxOut,
           uint32_t* __restrict__ candOut, int* __restrict__ counts) {
    const int v = blockIdx.x >> 11;
    const int t = blockIdx.x & 2047;
    const int b = threadIdx.x >> 5;
    const int lane = threadIdx.x & 31;

    const uint32_t base = (uint32_t)t * 8192u + (uint32_t)v * 512u +
                          ((uint32_t)b << 24) + (uint32_t)lane;
    uint32_t r[16];
    uint32_t m = 0u;
#pragma unroll
    for (int j = 0; j < 16; j++) {
        r[j] = tf_bits(base + 32u * j);
        m = max(m, r[j]);
    }
#pragma unroll
    for (int o = 16; o; o >>= 1) m = max(m, __shfl_xor_sync(0xffffffffu, m, o));

    const float gmax = gumbel_from_ubits(m >> 9);
    const float glo = gmax - gdelta[v];
    const float ulo = expf(-(expf(-glo) - 1e-8f)) - 1e-8f;
    const int it = (int)floorf(ulo * 8388608.0f) - 16;
    const uint32_t thr = ((uint32_t)max(it, 0)) << 9;

    const int group = (b * TT + t) * VV + v;
    int cnt = 0;
    int firstK = 0;
#pragma unroll
    for (int j = 0; j < 16; j++) {
        unsigned mask = __ballot_sync(0xffffffffu, r[j] >= thr);
        while (mask) {
            const int src = __ffs(mask) - 1;
            mask &= mask - 1;
            const int kc = 32 * j + src;
            const uint32_t ub = __shfl_sync(0xffffffffu, r[j], src) >> 9;
            if (lane == 0 && cnt < 8)
                candOut[group * 8 + cnt] = (ub << 9) | (uint32_t)kc;
            if (cnt == 0) firstK = kc;
            cnt++;
        }
    }
    if (lane == 0) {
        if (cnt == 1) {
            idxOut[group] = firstK;
            atomicAdd(&counts[v * KK + firstK], 1);
        } else {
            idxOut[group] = -min(cnt, 8);   // unresolved marker
        }
    }
}

// ---------------------------------------------------------------------------
// resolve_k: exact scores for multi-candidate groups (needs Q). One thread
// per group; most threads exit immediately.
// ---------------------------------------------------------------------------
__global__ __launch_bounds__(256)
void resolve_k(const float* __restrict__ Q, const float* __restrict__ cbk,
               const uint32_t* __restrict__ cand,
               int* __restrict__ idxOut, int* __restrict__ counts) {
    const int g = blockIdx.x * 256 + threadIdx.x;
    const int marker = idxOut[g];
    if (marker >= 0) return;
    const int n = -marker;
    const int v = g & 15;
    const int row = g >> 4;
    const float* q = Q + (size_t)row * DD + v * DG;

    float q2 = 0.0f;
#pragma unroll
    for (int d = 0; d < DG; d += 4) {
        float4 x = *(const float4*)(q + d);
        q2 += x.x * x.x + x.y * x.y + x.z * x.z + x.w * x.w;
    }

    float bestS = -3.4e38f;
    int bestK = 0;
    for (int c = 0; c < n; c++) {
        const uint32_t wd = cand[g * 8 + c];
        const int k = (int)(wd & 511u);
        const uint32_t ub = wd >> 9;
        const float* cr = cbk + (((size_t)v * KK + k) << 6);
        float qc = 0.0f, c2 = 0.0f;
#pragma unroll
        for (int d = 0; d < DG; d += 4) {
            float4 x = *(const float4*)(q + d);
            float4 y = *(const float4*)(cr + d);
            qc += x.x * y.x + x.y * y.y + x.z * y.z + x.w * y.w;
            c2 += y.x * y.x + y.y * y.y + y.z * y.z + y.w * y.w;
        }
        const float dist = sqrtf(fmaxf(q2 + c2 - 2.0f * qc, 0.0f));
        const float s = gumbel_from_ubits(ub) - dist;
        if (s > bestS) { bestS = s; bestK = k; }   // ascending k: ties -> earliest
    }
    idxOut[g] = bestK;
    atomicAdd(&counts[v * KK + bestK], 1);
}

// ---------------------------------------------------------------------------
// gather_sum: quantized[b,t] = sum_v P[v][idx_v]; also emits targets.
// ---------------------------------------------------------------------------
__global__ __launch_bounds__(128)
void gather_sum(const float* __restrict__ P, const int* __restrict__ idx,
                float* __restrict__ out) {
    __shared__ int sidx[VV];
    const int row = blockIdx.x;
    const int tid = threadIdx.x;
    if (tid < VV) sidx[tid] = idx[row * VV + tid];
    __syncthreads();

    const int n = tid * 8;
    float4 a0 = make_float4(0.f, 0.f, 0.f, 0.f);
    float4 a1 = make_float4(0.f, 0.f, 0.f, 0.f);
#pragma unroll
    for (int v = 0; v < VV; v++) {
        const float* p = P + ((((size_t)v << 9) + sidx[v]) << 10) + n;
        float4 x = *(const float4*)(p + 0);
        float4 y = *(const float4*)(p + 4);
        a0.x += x.x; a0.y += x.y; a0.z += x.z; a0.w += x.w;
        a1.x += y.x; a1.y += y.y; a1.z += y.z; a1.w += y.w;
    }
    float* o = out + (size_t)row * DD + n;
    *(float4*)(o + 0) = a0;
    *(float4*)(o + 4) = a1;

    if (tid == 0) {
        int s = 0;
#pragma unroll
        for (int v = 0; v < VV; v++) s += sidx[v] * (v * KK);
        out[OUT_TARGETS + row] = (float)s;
    }
}

// ---------------------------------------------------------------------------
// Small kernels
// ---------------------------------------------------------------------------
__global__ void zero_counts_k(int* __restrict__ counts) {
    int i = blockIdx.x * blockDim.x + threadIdx.x;
    if (i < VV * KK) counts[i] = 0;
}

__global__ void loss_k(const int* __restrict__ counts, float* __restrict__ out) {
    __shared__ float ent_s[VV];
    const int tid = threadIdx.x, lane = tid & 31, w = tid >> 5;
    if (w < VV) {
        float tot = 0.0f;
        for (int kk = lane; kk < KK; kk += 32) tot += (float)counts[w * KK + kk];
#pragma unroll
        for (int o = 16; o; o >>= 1) tot += __shfl_xor_sync(0xffffffffu, tot, o);
        float inv = 1.0f / tot;
        float pl = 0.0f;
        for (int kk = lane; kk < KK; kk += 32) {
            float p = (float)counts[w * KK + kk] * inv;
            pl += p * logf(p + 1e-8f);
        }
#pragma unroll
        for (int o = 16; o; o >>= 1) pl += __shfl_xor_sync(0xffffffffu, pl, o);
        if (lane == 0) ent_s[w] = -pl;
    }
    __syncthreads();
    if (tid == 0) {
        float lk = logf(512.0f);
        float acc = 0.0f;
#pragma unroll
        for (int v = 0; v < VV; v++) acc += ent_s[v] / lk;
        float diversity = -(acc / (float)VV);
        out[OUT_LOSS] = 0.1f * diversity;
    }
}

// ---------------------------------------------------------------------------
// Launch: fork rng/pmat branch onto a second stream so the ALU-bound RNG
// work overlaps with the tensor-bound GEMM. Streams/events are created once
// on the first (non-captured) correctness call; replays reuse them.
// ---------------------------------------------------------------------------
extern "C" void kernel_launch(void* const* d_in, const int* in_sizes, int n_in,
                              void* d_out, int out_size) {
    const float* features  = (const float*)d_in[0];
    const float* codebooks = (const float*)d_in[1];
    const float* Wq        = (const float*)d_in[2];
    const float* bq        = (const float*)d_in[3];
    const float* Wout      = (const float*)d_in[4];
    const float* bout      = (const float*)d_in[5];
    float* out = (float*)d_out;

    float* Qb;  cudaGetSymbolAddress((void**)&Qb,  g_Q);
    float* Pb;  cudaGetSymbolAddress((void**)&Pb,  g_P);
    float* WhP; cudaGetSymbolAddress((void**)&WhP, g_Wh);
    float* WlP; cudaGetSymbolAddress((void**)&WlP, g_Wl);
    int* idxP;  cudaGetSymbolAddress((void**)&idxP, g_idx);
    uint32_t* candP; cudaGetSymbolAddress((void**)&candP, g_cand);
    int* cntP;  cudaGetSymbolAddress((void**)&cntP, g_counts);
    float* dP;  cudaGetSymbolAddress((void**)&dP,  g_delta);

    static cudaStream_t sB = nullptr;
    static cudaEvent_t evF = nullptr, evJ = nullptr;
    if (sB == nullptr) {
        cudaStreamCreateWithFlags(&sB, cudaStreamNonBlocking);
        cudaEventCreateWithFlags(&evF, cudaEventDisableTiming);
        cudaEventCreateWithFlags(&evJ, cudaEventDisableTiming);
        cudaFuncSetAttribute(gemm_mma3,
                             cudaFuncAttributeMaxDynamicSharedMemorySize,
                             G2_BYTES);
    }

    // fork
    cudaEventRecord(evF, 0);
    cudaStreamWaitEvent(sB, evF, 0);

    // branch B (no Q dependency): counts/delta/rng/pmat
    zero_counts_k<<<16, 512, 0, sB>>>(cntP);
    delta_k<<<VV, 512, 0, sB>>>(codebooks, dP);
    rng_k<<<VV * TT, 256, 0, sB>>>(dP, idxP, candP, cntP);
    pmat_k<<<dim3(8, 8, VV), 256, 0, sB>>>(codebooks, Wout, bout, Pb);
    cudaEventRecord(evJ, sB);

    // branch A (default stream): Wq projection
    wsplit_k<<<DD * DD / 1024, 256>>>(Wq, WhP, WlP);
    gemm_mma3<<<dim3(8, 128), 512, G2_BYTES>>>(features, WhP, WlP, bq, Qb);

    // join
    cudaStreamWaitEvent(0, evJ, 0);
    resolve_k<<<NGRP / 256, 256>>>(Qb, codebooks, candP, idxP, cntP);
    gather_sum<<<MROWS, 128>>>(Pb, idxP, out);
    loss_k<<<1, 512>>>(cntP, out);
}

// round 9
// speedup vs baseline: 1.7741x; 1.6275x over previous
#include <cuda_runtime.h>
#include <cstdint>

// ---------------------------------------------------------------------------
// GumbelVectorQuantizer forward, GB300.
// B=8, T=2048, D=1024, V=16, K=512, d=64.
// ---------------------------------------------------------------------------

#define BB   8
#define TT   2048
#define DD   1024
#define VV   16
#define KK   512
#define DG   64
#define MROWS (BB * TT)          // 16384
#define NGRP  (MROWS * VV)       // 262144
#define UCAP  4096               // per-v unresolved-slot capacity (mean ~1300, 80 sigma)

#define OUT_QUANT   0
#define OUT_TARGETS (MROWS * DD)            // 16777216
#define OUT_LOSS    (MROWS * DD + MROWS)    // 16793600

// Scratch (device globals: allocation-free contract)
__device__ float    g_P[VV * KK * DD];     // P[v][k][:] = codebooks[v][k] @ Wout_v^T (+bout at v=0)
__device__ int      g_idx[NGRP];           // final idx, or -(1+(slot<<4)+n) marker
__device__ uint32_t g_cand[NGRP * 8];      // packed (ubits<<9)|k per candidate
__device__ int      g_counts[VV * KK];     // codebook usage counts
__device__ float    g_delta[VV];           // per-group safe score window
__device__ int      g_ucnt[VV];            // unresolved count per v
__device__ int      g_ulist[VV * UCAP];    // unresolved row ids per v
__device__ float    g_qsel[VV * UCAP * DG];// q slices for unresolved groups

// ---------------------------------------------------------------------------
// Threefry2x32, JAX partitionable path, key = (0, 42).
// ---------------------------------------------------------------------------
__device__ __forceinline__ uint32_t rotl32(uint32_t x, int r) {
    return __funnelshift_l(x, x, r);
}
__device__ __forceinline__ void tf_round(uint32_t& x0, uint32_t& x1, int r) {
    x0 += x1;
    x1 = rotl32(x1, r);
    x1 ^= x0;
}
__device__ __forceinline__ uint32_t tf_bits(uint32_t i) {
    const uint32_t ks0 = 0u;
    const uint32_t ks1 = 42u;
    const uint32_t ks2 = 0x1BD11BDAu ^ ks0 ^ ks1;
    uint32_t x0 = 0u + ks0;
    uint32_t x1 = i + ks1;
    tf_round(x0, x1, 13); tf_round(x0, x1, 15); tf_round(x0, x1, 26); tf_round(x0, x1, 6);
    x0 += ks1; x1 += ks2 + 1u;
    tf_round(x0, x1, 17); tf_round(x0, x1, 29); tf_round(x0, x1, 16); tf_round(x0, x1, 24);
    x0 += ks2; x1 += ks0 + 2u;
    tf_round(x0, x1, 13); tf_round(x0, x1, 15); tf_round(x0, x1, 26); tf_round(x0, x1, 6);
    x0 += ks0; x1 += ks1 + 3u;
    tf_round(x0, x1, 17); tf_round(x0, x1, 29); tf_round(x0, x1, 16); tf_round(x0, x1, 24);
    x0 += ks1; x1 += ks2 + 4u;
    tf_round(x0, x1, 13); tf_round(x0, x1, 15); tf_round(x0, x1, 26); tf_round(x0, x1, 6);
    x0 += ks2; x1 += ks0 + 5u;
    return x0 ^ x1;
}

__device__ __forceinline__ float gumbel_from_ubits(uint32_t ub) {
    float u = __uint_as_float(0x3f800000u | ub) - 1.0f;
    return -logf(-logf(u + 1e-8f) + 1e-8f);
}

// ---------------------------------------------------------------------------
// delta_k: per-v safe window  Delta_v = 2*max_k ||c_k|| + margin
// ---------------------------------------------------------------------------
__global__ void delta_k(const float* __restrict__ cbk, float* __restrict__ gd) {
    __shared__ float red[16];
    const int v = blockIdx.x;
    const int k = threadIdx.x;
    const int lane = k & 31, w = k >> 5;
    const float* crow = cbk + ((size_t)(v * KK + k)) * DG;
    float s = 0.0f;
#pragma unroll
    for (int d = 0; d < DG; d += 4) {
        float4 c = *(const float4*)(crow + d);
        s += c.x * c.x + c.y * c.y + c.z * c.z + c.w * c.w;
    }
#pragma unroll
    for (int o = 16; o; o >>= 1) s = fmaxf(s, __shfl_xor_sync(0xffffffffu, s, o));
    if (lane == 0) red[w] = s;
    __syncthreads();
    if (k == 0) {
        float m = 0.0f;
#pragma unroll
        for (int i = 0; i < 16; i++) m = fmaxf(m, red[i]);
        gd[v] = 2.0f * sqrtf(m) + 0.05f;
    }
}

// ---------------------------------------------------------------------------
// rng_k: threefry + integer max + threshold + candidate collection.
// Single-candidate groups finalize idx+counts; multi-candidate groups get a
// slot in the per-v unresolved list.
// ---------------------------------------------------------------------------
__global__ __launch_bounds__(256)
void rng_k(const float* __restrict__ gdelta, int* __restrict__ idxOut,
           uint32_t* __restrict__ candOut, int* __restrict__ counts,
           int* __restrict__ ucnt, int* __restrict__ ulist) {
    const int v = blockIdx.x >> 11;
    const int t = blockIdx.x & 2047;
    const int b = threadIdx.x >> 5;
    const int lane = threadIdx.x & 31;

    const uint32_t base = (uint32_t)t * 8192u + (uint32_t)v * 512u +
                          ((uint32_t)b << 24) + (uint32_t)lane;
    uint32_t r[16];
    uint32_t m = 0u;
#pragma unroll
    for (int j = 0; j < 16; j++) {
        r[j] = tf_bits(base + 32u * j);
        m = max(m, r[j]);
    }
#pragma unroll
    for (int o = 16; o; o >>= 1) m = max(m, __shfl_xor_sync(0xffffffffu, m, o));

    const float gmax = gumbel_from_ubits(m >> 9);
    const float glo = gmax - gdelta[v];
    const float ulo = expf(-(expf(-glo) - 1e-8f)) - 1e-8f;
    const int it = (int)floorf(ulo * 8388608.0f) - 16;
    const uint32_t thr = ((uint32_t)max(it, 0)) << 9;

    const int row = b * TT + t;
    const int group = row * VV + v;
    int cnt = 0;
    int firstK = 0;
#pragma unroll
    for (int j = 0; j < 16; j++) {
        unsigned mask = __ballot_sync(0xffffffffu, r[j] >= thr);
        while (mask) {
            const int src = __ffs(mask) - 1;
            mask &= mask - 1;
            const int kc = 32 * j + src;
            const uint32_t ub = __shfl_sync(0xffffffffu, r[j], src) >> 9;
            if (lane == 0 && cnt < 8)
                candOut[group * 8 + cnt] = (ub << 9) | (uint32_t)kc;
            if (cnt == 0) firstK = kc;
            cnt++;
        }
    }
    if (lane == 0) {
        if (cnt == 1) {
            idxOut[group] = firstK;
            atomicAdd(&counts[v * KK + firstK], 1);
        } else {
            int slot = atomicAdd(&ucnt[v], 1);
            slot = min(slot, UCAP - 1);   // statistically unreachable guard
            ulist[v * UCAP + slot] = row;
            idxOut[group] = -(1 + (slot << 4) + min(cnt, 8));
        }
    }
}

// ---------------------------------------------------------------------------
// qproj_k: selective q projection. For each unresolved (v, slot):
//   qsel[v][slot][d] = features[row] . Wq[v*64+d] + bq[v*64+d]
// grid (64 chunks, 16 v), block 256, tile M=64 slots x N=64 d, BK=16.
// ---------------------------------------------------------------------------
__global__ __launch_bounds__(256)
void qproj_k(const float* __restrict__ feats, const float* __restrict__ Wq,
             const float* __restrict__ bq, const int* __restrict__ ucnt,
             const int* __restrict__ ulist, float* __restrict__ qsel) {
    __shared__ float As[16][68];
    __shared__ float Ws[16][68];
    __shared__ int rows[64];

    const int v = blockIdx.y;
    const int chunk = blockIdx.x;
    const int count = min(ucnt[v], UCAP);
    const int base = chunk * 64;
    if (base >= count) return;

    const int tid = threadIdx.x;
    if (tid < 64) rows[tid] = ulist[v * UCAP + min(base + tid, count - 1)];
    __syncthreads();

    const int lrow = tid >> 2;            // 0..63 (A slot row / W d row)
    const int lcol = (tid & 3) * 4;       // 0,4,8,12
    const float* Ag = feats + (size_t)rows[lrow] * DD + lcol;
    const float* Wg = Wq + (size_t)(v * DG + lrow) * DD + lcol;

    const int tx = tid & 15;              // n (d) tile
    const int ty = tid >> 4;              // m (slot) tile
    float acc[4][4];
#pragma unroll
    for (int i = 0; i < 4; i++)
#pragma unroll
        for (int j = 0; j < 4; j++) acc[i][j] = 0.0f;

    for (int k0 = 0; k0 < DD; k0 += 16) {
        float4 a = *(const float4*)(Ag + k0);
        float4 w = *(const float4*)(Wg + k0);
        __syncthreads();
        As[lcol + 0][lrow] = a.x; As[lcol + 1][lrow] = a.y;
        As[lcol + 2][lrow] = a.z; As[lcol + 3][lrow] = a.w;
        Ws[lcol + 0][lrow] = w.x; Ws[lcol + 1][lrow] = w.y;
        Ws[lcol + 2][lrow] = w.z; Ws[lcol + 3][lrow] = w.w;
        __syncthreads();
#pragma unroll
        for (int kk = 0; kk < 16; kk++) {
            float4 rm = *(const float4*)&As[kk][ty * 4];
            float4 rn = *(const float4*)&Ws[kk][tx * 4];
            float m0 = rm.x, m1 = rm.y, m2 = rm.z, m3 = rm.w;
            float n0 = rn.x, n1 = rn.y, n2 = rn.z, n3 = rn.w;
            acc[0][0] = fmaf(m0, n0, acc[0][0]); acc[0][1] = fmaf(m0, n1, acc[0][1]);
            acc[0][2] = fmaf(m0, n2, acc[0][2]); acc[0][3] = fmaf(m0, n3, acc[0][3]);
            acc[1][0] = fmaf(m1, n0, acc[1][0]); acc[1][1] = fmaf(m1, n1, acc[1][1]);
            acc[1][2] = fmaf(m1, n2, acc[1][2]); acc[1][3] = fmaf(m1, n3, acc[1][3]);
            acc[2][0] = fmaf(m2, n0, acc[2][0]); acc[2][1] = fmaf(m2, n1, acc[2][1]);
            acc[2][2] = fmaf(m2, n2, acc[2][2]); acc[2][3] = fmaf(m2, n3, acc[2][3]);
            acc[3][0] = fmaf(m3, n0, acc[3][0]); acc[3][1] = fmaf(m3, n1, acc[3][1]);
            acc[3][2] = fmaf(m3, n2, acc[3][2]); acc[3][3] = fmaf(m3, n3, acc[3][3]);
        }
    }

    const float4 bq4 = *(const float4*)(bq + v * DG + tx * 4);
#pragma unroll
    for (int i = 0; i < 4; i++) {
        const int sl = ty * 4 + i;
        if (base + sl < count) {
            float4 o;
            o.x = acc[i][0] + bq4.x; o.y = acc[i][1] + bq4.y;
            o.z = acc[i][2] + bq4.z; o.w = acc[i][3] + bq4.w;
            *(float4*)(qsel + ((size_t)(v * UCAP + base + sl)) * DG + tx * 4) = o;
        }
    }
}

// ---------------------------------------------------------------------------
// resolve_k: exact scores for multi-candidate groups using qsel slices.
// ---------------------------------------------------------------------------
__global__ __launch_bounds__(256)
void resolve_k(const float* __restrict__ qsel, const float* __restrict__ cbk,
               const uint32_t* __restrict__ cand,
               int* __restrict__ idxOut, int* __restrict__ counts) {
    const int g = blockIdx.x * 256 + threadIdx.x;
    const int marker = idxOut[g];
    if (marker >= 0) return;
    const int x = -marker - 1;
    const int n = x & 15;
    const int slot = x >> 4;
    const int v = g & 15;
    const float* q = qsel + ((size_t)(v * UCAP + slot)) * DG;

    float q2 = 0.0f;
#pragma unroll
    for (int d = 0; d < DG; d += 4) {
        float4 y = *(const float4*)(q + d);
        q2 += y.x * y.x + y.y * y.y + y.z * y.z + y.w * y.w;
    }

    float bestS = -3.4e38f;
    int bestK = 0;
    for (int c = 0; c < n; c++) {
        const uint32_t wd = cand[g * 8 + c];
        const int k = (int)(wd & 511u);
        const uint32_t ub = wd >> 9;
        const float* cr = cbk + (((size_t)v * KK + k) << 6);
        float qc = 0.0f, c2 = 0.0f;
#pragma unroll
        for (int d = 0; d < DG; d += 4) {
            float4 xq = *(const float4*)(q + d);
            float4 yc = *(const float4*)(cr + d);
            qc += xq.x * yc.x + xq.y * yc.y + xq.z * yc.z + xq.w * yc.w;
            c2 += yc.x * yc.x + yc.y * yc.y + yc.z * yc.z + yc.w * yc.w;
        }
        const float dist = sqrtf(fmaxf(q2 + c2 - 2.0f * qc, 0.0f));
        const float s = gumbel_from_ubits(ub) - dist;
        if (s > bestS) { bestS = s; bestK = k; }   // ascending k: ties -> earliest
    }
    idxOut[g] = bestK;
    atomicAdd(&counts[v * KK + bestK], 1);
}

// ===========================================================================
// pmat: P[v][k][n] = sum_d codebooks[v][k][d] * Wout[n][v*64+d]  (+bout[n] @ v==0)
// ===========================================================================
__global__ __launch_bounds__(256)
void pmat_k(const float* __restrict__ cbk, const float* __restrict__ Wout,
            const float* __restrict__ bout, float* __restrict__ P) {
    __shared__ float Ct[64][65];
    __shared__ float Wt[128][65];
    const int v = blockIdx.z;
    const int k0 = blockIdx.y * 64;
    const int n0 = blockIdx.x * 128;
    const int tid = threadIdx.x;

    for (int i = tid; i < 64 * 16; i += 256) {
        int rr = i >> 4, dq = (i & 15) * 4;
        float4 c = *(const float4*)(cbk + (((size_t)v * KK + k0 + rr) << 6) + dq);
        Ct[rr][dq + 0] = c.x; Ct[rr][dq + 1] = c.y;
        Ct[rr][dq + 2] = c.z; Ct[rr][dq + 3] = c.w;
    }
    for (int i = tid; i < 128 * 16; i += 256) {
        int rr = i >> 4, dq = (i & 15) * 4;
        float4 wv = *(const float4*)(Wout + (size_t)(n0 + rr) * DD + v * DG + dq);
        Wt[rr][dq + 0] = wv.x; Wt[rr][dq + 1] = wv.y;
        Wt[rr][dq + 2] = wv.z; Wt[rr][dq + 3] = wv.w;
    }
    __syncthreads();

    const int ks = (tid >> 4) * 4;
    const int ns = (tid & 15) * 8;
    float acc[4][8];
#pragma unroll
    for (int i = 0; i < 4; i++)
#pragma unroll
        for (int j = 0; j < 8; j++) acc[i][j] = 0.0f;

#pragma unroll 8
    for (int d = 0; d < 64; d++) {
        float cv[4], wv[8];
#pragma unroll
        for (int i = 0; i < 4; i++) cv[i] = Ct[ks + i][d];
#pragma unroll
        for (int j = 0; j < 8; j++) wv[j] = Wt[ns + j][d];
#pragma unroll
        for (int i = 0; i < 4; i++)
#pragma unroll
            for (int j = 0; j < 8; j++)
                acc[i][j] = fmaf(cv[i], wv[j], acc[i][j]);
    }

#pragma unroll
    for (int i = 0; i < 4; i++) {
        float* prow = P + (((size_t)v * KK + k0 + ks + i) << 10) + n0 + ns;
        float4 o0, o1;
        float b0 = 0, b1 = 0, b2 = 0, b3 = 0, b4 = 0, b5 = 0, b6 = 0, b7 = 0;
        if (v == 0) {
            b0 = bout[n0 + ns + 0]; b1 = bout[n0 + ns + 1];
            b2 = bout[n0 + ns + 2]; b3 = bout[n0 + ns + 3];
            b4 = bout[n0 + ns + 4]; b5 = bout[n0 + ns + 5];
            b6 = bout[n0 + ns + 6]; b7 = bout[n0 + ns + 7];
        }
        o0.x = acc[i][0] + b0; o0.y = acc[i][1] + b1;
        o0.z = acc[i][2] + b2; o0.w = acc[i][3] + b3;
        o1.x = acc[i][4] + b4; o1.y = acc[i][5] + b5;
        o1.z = acc[i][6] + b6; o1.w = acc[i][7] + b7;
        *(float4*)(prow + 0) = o0;
        *(float4*)(prow + 4) = o1;
    }
}

// ---------------------------------------------------------------------------
// gather_sum: quantized[b,t] = sum_v P[v][idx_v]; also emits targets.
// ---------------------------------------------------------------------------
__global__ __launch_bounds__(128)
void gather_sum(const float* __restrict__ P, const int* __restrict__ idx,
                float* __restrict__ out) {
    __shared__ int sidx[VV];
    const int row = blockIdx.x;
    const int tid = threadIdx.x;
    if (tid < VV) sidx[tid] = idx[row * VV + tid];
    __syncthreads();

    const int n = tid * 8;
    float4 a0 = make_float4(0.f, 0.f, 0.f, 0.f);
    float4 a1 = make_float4(0.f, 0.f, 0.f, 0.f);
#pragma unroll
    for (int v = 0; v < VV; v++) {
        const float* p = P + ((((size_t)v << 9) + sidx[v]) << 10) + n;
        float4 x = *(const float4*)(p + 0);
        float4 y = *(const float4*)(p + 4);
        a0.x += x.x; a0.y += x.y; a0.z += x.z; a0.w += x.w;
        a1.x += y.x; a1.y += y.y; a1.z += y.z; a1.w += y.w;
    }
    float* o = out + (size_t)row * DD + n;
    *(float4*)(o + 0) = a0;
    *(float4*)(o + 4) = a1;

    if (tid == 0) {
        int s = 0;
#pragma unroll
        for (int v = 0; v < VV; v++) s += sidx[v] * (v * KK);
        out[OUT_TARGETS + row] = (float)s;
    }
}

// ---------------------------------------------------------------------------
// Small kernels
// ---------------------------------------------------------------------------
__global__ void zero_counts_k(int* __restrict__ counts, int* __restrict__ ucnt) {
    int i = blockIdx.x * blockDim.x + threadIdx.x;
    if (i < VV * KK) counts[i] = 0;
    if (i < VV) ucnt[i] = 0;
}

__global__ void loss_k(const int* __restrict__ counts, float* __restrict__ out) {
    __shared__ float ent_s[VV];
    const int tid = threadIdx.x, lane = tid & 31, w = tid >> 5;
    if (w < VV) {
        float tot = 0.0f;
        for (int kk = lane; kk < KK; kk += 32) tot += (float)counts[w * KK + kk];
#pragma unroll
        for (int o = 16; o; o >>= 1) tot += __shfl_xor_sync(0xffffffffu, tot, o);
        float inv = 1.0f / tot;
        float pl = 0.0f;
        for (int kk = lane; kk < KK; kk += 32) {
            float p = (float)counts[w * KK + kk] * inv;
            pl += p * logf(p + 1e-8f);
        }
#pragma unroll
        for (int o = 16; o; o >>= 1) pl += __shfl_xor_sync(0xffffffffu, pl, o);
        if (lane == 0) ent_s[w] = -pl;
    }
    __syncthreads();
    if (tid == 0) {
        float lk = logf(512.0f);
        float acc = 0.0f;
#pragma unroll
        for (int v = 0; v < VV; v++) acc += ent_s[v] / lk;
        float diversity = -(acc / (float)VV);
        out[OUT_LOSS] = 0.1f * diversity;
    }
}

// ---------------------------------------------------------------------------
// Launch
// ---------------------------------------------------------------------------
extern "C" void kernel_launch(void* const* d_in, const int* in_sizes, int n_in,
                              void* d_out, int out_size) {
    const float* features  = (const float*)d_in[0];
    const float* codebooks = (const float*)d_in[1];
    const float* Wq        = (const float*)d_in[2];
    const float* bq        = (const float*)d_in[3];
    const float* Wout      = (const float*)d_in[4];
    const float* bout      = (const float*)d_in[5];
    float* out = (float*)d_out;

    float* Pb;  cudaGetSymbolAddress((void**)&Pb,  g_P);
    int* idxP;  cudaGetSymbolAddress((void**)&idxP, g_idx);
    uint32_t* candP; cudaGetSymbolAddress((void**)&candP, g_cand);
    int* cntP;  cudaGetSymbolAddress((void**)&cntP, g_counts);
    float* dP;  cudaGetSymbolAddress((void**)&dP,  g_delta);
    int* ucP;   cudaGetSymbolAddress((void**)&ucP, g_ucnt);
    int* ulP;   cudaGetSymbolAddress((void**)&ulP, g_ulist);
    float* qsP; cudaGetSymbolAddress((void**)&qsP, g_qsel);

    static cudaStream_t sB = nullptr;
    static cudaEvent_t evF = nullptr, evJ = nullptr;
    if (sB == nullptr) {
        cudaStreamCreateWithFlags(&sB, cudaStreamNonBlocking);
        cudaEventCreateWithFlags(&evF, cudaEventDisableTiming);
        cudaEventCreateWithFlags(&evJ, cudaEventDisableTiming);
    }

    // fork: pmat (independent of everything on the main chain)
    cudaEventRecord(evF, 0);
    cudaStreamWaitEvent(sB, evF, 0);
    pmat_k<<<dim3(8, 8, VV), 256, 0, sB>>>(codebooks, Wout, bout, Pb);
    cudaEventRecord(evJ, sB);

    // main chain
    zero_counts_k<<<16, 512>>>(cntP, ucP);
    delta_k<<<VV, 512>>>(codebooks, dP);
    rng_k<<<VV * TT, 256>>>(dP, idxP, candP, cntP, ucP, ulP);
    qproj_k<<<dim3(UCAP / 64, VV), 256>>>(features, Wq, bq, ucP, ulP, qsP);
    resolve_k<<<NGRP / 256, 256>>>(qsP, codebooks, candP, idxP, cntP);
    cudaStreamWaitEvent(0, evJ, 0);
    gather_sum<<<MROWS, 128>>>(Pb, idxP, out);
    loss_k<<<1, 512>>>(cntP, out);
}

// round 10
// speedup vs baseline: 1.9065x; 1.0746x over previous
#include <cuda_runtime.h>
#include <cstdint>

// ---------------------------------------------------------------------------
// GumbelVectorQuantizer forward, GB300.
// B=8, T=2048, D=1024, V=16, K=512, d=64.
// ---------------------------------------------------------------------------

#define BB   8
#define TT   2048
#define DD   1024
#define VV   16
#define KK   512
#define DG   64
#define MROWS (BB * TT)          // 16384
#define NGRP  (MROWS * VV)       // 262144
#define UCAP  4096               // per-v unresolved-slot capacity (mean ~450 now)

#define OUT_QUANT   0
#define OUT_TARGETS (MROWS * DD)            // 16777216
#define OUT_LOSS    (MROWS * DD + MROWS)    // 16793600

// Scratch (device globals: allocation-free contract)
__device__ float    g_P[VV * KK * DD];     // P[v][k][:] = codebooks[v][k] @ Wout_v^T (+bout at v=0)
__device__ int      g_idx[NGRP];           // final idx, or -(1+(slot<<4)+n) marker
__device__ uint32_t g_cand[NGRP * 8];      // packed (ubits<<9)|k per candidate
__device__ int      g_counts[VV * KK];     // codebook usage counts
__device__ float    g_delta[VV];           // per-group safe score window
__device__ int      g_ucnt[VV];            // unresolved count per v
__device__ int      g_ulist[VV * UCAP];    // unresolved row ids per v
__device__ float    g_qsel[VV * UCAP * DG];// q slices for unresolved groups

// ---------------------------------------------------------------------------
// Threefry2x32, JAX partitionable path, key = (0, 42).
// Bit-identical to the reference; injections fused into IADD3-friendly
// three-term adds to cut issue count (rng_k is issue-bound).
// ---------------------------------------------------------------------------
__device__ __forceinline__ uint32_t rotl32(uint32_t x, int r) {
    return __funnelshift_l(x, x, r);
}

#define TFR(r)            { x0 += x1; x1 = rotl32(x1, (r)) ^ x0; }
#define TFINJR(ka, kb, r) { x1 += (kb); x0 = x0 + (ka) + x1; \
                            x1 = rotl32(x1, (r)) ^ x0; }

__device__ __forceinline__ uint32_t tf_bits(uint32_t i) {
    const uint32_t KS1 = 42u;
    const uint32_t KS2 = 0x1BD11BDAu ^ 42u;   // 0x1BD11BF0
    uint32_t x1 = i + KS1;
    uint32_t x0 = x1;                          // round 1 with x0 = 0
    x1 = rotl32(x1, 13) ^ x0;
    TFR(15); TFR(26); TFR(6);
    TFINJR(KS1, KS2 + 1u, 17); TFR(29); TFR(16); TFR(24);
    TFINJR(KS2, 2u, 13);       TFR(15); TFR(26); TFR(6);
    TFINJR(0u, KS1 + 3u, 17);  TFR(29); TFR(16); TFR(24);
    TFINJR(KS1, KS2 + 4u, 13); TFR(15); TFR(26); TFR(6);
    x0 += KS2;
    x1 += 5u;
    return x0 ^ x1;
}

__device__ __forceinline__ float gumbel_from_ubits(uint32_t ub) {
    float u = __uint_as_float(0x3f800000u | ub) - 1.0f;
    return -logf(-logf(u + 1e-8f) + 1e-8f);
}

// ---------------------------------------------------------------------------
// delta_k: per-v safe window  Delta_v = 2*max_k ||c_k|| + margin.
// Margin covers fp error in score comparison (~2e-6); 0.005 is 2000x that.
// ---------------------------------------------------------------------------
__global__ void delta_k(const float* __restrict__ cbk, float* __restrict__ gd) {
    __shared__ float red[16];
    const int v = blockIdx.x;
    const int k = threadIdx.x;
    const int lane = k & 31, w = k >> 5;
    const float* crow = cbk + ((size_t)(v * KK + k)) * DG;
    float s = 0.0f;
#pragma unroll
    for (int d = 0; d < DG; d += 4) {
        float4 c = *(const float4*)(crow + d);
        s += c.x * c.x + c.y * c.y + c.z * c.z + c.w * c.w;
    }
#pragma unroll
    for (int o = 16; o; o >>= 1) s = fmaxf(s, __shfl_xor_sync(0xffffffffu, s, o));
    if (lane == 0) red[w] = s;
    __syncthreads();
    if (k == 0) {
        float m = 0.0f;
#pragma unroll
        for (int i = 0; i < 16; i++) m = fmaxf(m, red[i]);
        gd[v] = 2.0f * sqrtf(m) + 0.005f;
    }
}

// ---------------------------------------------------------------------------
// rng_k: threefry + integer max + threshold + candidate collection.
// ---------------------------------------------------------------------------
__global__ __launch_bounds__(256)
void rng_k(const float* __restrict__ gdelta, int* __restrict__ idxOut,
           uint32_t* __restrict__ candOut, int* __restrict__ counts,
           int* __restrict__ ucnt, int* __restrict__ ulist) {
    const int v = blockIdx.x >> 11;
    const int t = blockIdx.x & 2047;
    const int b = threadIdx.x >> 5;
    const int lane = threadIdx.x & 31;

    const uint32_t base = (uint32_t)t * 8192u + (uint32_t)v * 512u +
                          ((uint32_t)b << 24) + (uint32_t)lane;
    uint32_t r[16];
    uint32_t m = 0u;
#pragma unroll
    for (int j = 0; j < 16; j++) {
        r[j] = tf_bits(base + 32u * j);
        m = max(m, r[j]);
    }
#pragma unroll
    for (int o = 16; o; o >>= 1) m = max(m, __shfl_xor_sync(0xffffffffu, m, o));

    const float gmax = gumbel_from_ubits(m >> 9);
    const float glo = gmax - gdelta[v];
    const float ulo = expf(-(expf(-glo) - 1e-8f)) - 1e-8f;
    const int it = (int)floorf(ulo * 8388608.0f) - 16;
    const uint32_t thr = ((uint32_t)max(it, 0)) << 9;

    const int row = b * TT + t;
    const int group = row * VV + v;
    int cnt = 0;
    int firstK = 0;
#pragma unroll
    for (int j = 0; j < 16; j++) {
        unsigned mask = __ballot_sync(0xffffffffu, r[j] >= thr);
        while (mask) {
            const int src = __ffs(mask) - 1;
            mask &= mask - 1;
            const int kc = 32 * j + src;
            const uint32_t ub = __shfl_sync(0xffffffffu, r[j], src) >> 9;
            if (lane == 0 && cnt < 8)
                candOut[group * 8 + cnt] = (ub << 9) | (uint32_t)kc;
            if (cnt == 0) firstK = kc;
            cnt++;
        }
    }
    if (lane == 0) {
        if (cnt == 1) {
            idxOut[group] = firstK;
            atomicAdd(&counts[v * KK + firstK], 1);
        } else {
            int slot = atomicAdd(&ucnt[v], 1);
            slot = min(slot, UCAP - 1);   // statistically unreachable guard
            ulist[v * UCAP + slot] = row;
            idxOut[group] = -(1 + (slot << 4) + min(cnt, 8));
        }
    }
}

// ---------------------------------------------------------------------------
// qproj_k: selective q projection for unresolved groups.
// grid (UCAP/64, 16 v), block 256; tile M=64 slots x N=64 d, BK=16.
// ---------------------------------------------------------------------------
__global__ __launch_bounds__(256)
void qproj_k(const float* __restrict__ feats, const float* __restrict__ Wq,
             const float* __restrict__ bq, const int* __restrict__ ucnt,
             const int* __restrict__ ulist, float* __restrict__ qsel) {
    __shared__ float As[16][68];
    __shared__ float Ws[16][68];
    __shared__ int rows[64];

    const int v = blockIdx.y;
    const int chunk = blockIdx.x;
    const int count = min(ucnt[v], UCAP);
    const int base = chunk * 64;
    if (base >= count) return;

    const int tid = threadIdx.x;
    if (tid < 64) rows[tid] = ulist[v * UCAP + min(base + tid, count - 1)];
    __syncthreads();

    const int lrow = tid >> 2;            // 0..63
    const int lcol = (tid & 3) * 4;       // 0,4,8,12
    const float* Ag = feats + (size_t)rows[lrow] * DD + lcol;
    const float* Wg = Wq + (size_t)(v * DG + lrow) * DD + lcol;

    const int tx = tid & 15;
    const int ty = tid >> 4;
    float acc[4][4];
#pragma unroll
    for (int i = 0; i < 4; i++)
#pragma unroll
        for (int j = 0; j < 4; j++) acc[i][j] = 0.0f;

    for (int k0 = 0; k0 < DD; k0 += 16) {
        float4 a = *(const float4*)(Ag + k0);
        float4 w = *(const float4*)(Wg + k0);
        __syncthreads();
        As[lcol + 0][lrow] = a.x; As[lcol + 1][lrow] = a.y;
        As[lcol + 2][lrow] = a.z; As[lcol + 3][lrow] = a.w;
        Ws[lcol + 0][lrow] = w.x; Ws[lcol + 1][lrow] = w.y;
        Ws[lcol + 2][lrow] = w.z; Ws[lcol + 3][lrow] = w.w;
        __syncthreads();
#pragma unroll
        for (int kk = 0; kk < 16; kk++) {
            float4 rm = *(const float4*)&As[kk][ty * 4];
            float4 rn = *(const float4*)&Ws[kk][tx * 4];
            float m0 = rm.x, m1 = rm.y, m2 = rm.z, m3 = rm.w;
            float n0 = rn.x, n1 = rn.y, n2 = rn.z, n3 = rn.w;
            acc[0][0] = fmaf(m0, n0, acc[0][0]); acc[0][1] = fmaf(m0, n1, acc[0][1]);
            acc[0][2] = fmaf(m0, n2, acc[0][2]); acc[0][3] = fmaf(m0, n3, acc[0][3]);
            acc[1][0] = fmaf(m1, n0, acc[1][0]); acc[1][1] = fmaf(m1, n1, acc[1][1]);
            acc[1][2] = fmaf(m1, n2, acc[1][2]); acc[1][3] = fmaf(m1, n3, acc[1][3]);
            acc[2][0] = fmaf(m2, n0, acc[2][0]); acc[2][1] = fmaf(m2, n1, acc[2][1]);
            acc[2][2] = fmaf(m2, n2, acc[2][2]); acc[2][3] = fmaf(m2, n3, acc[2][3]);
            acc[3][0] = fmaf(m3, n0, acc[3][0]); acc[3][1] = fmaf(m3, n1, acc[3][1]);
            acc[3][2] = fmaf(m3, n2, acc[3][2]); acc[3][3] = fmaf(m3, n3, acc[3][3]);
        }
    }

    const float4 bq4 = *(const float4*)(bq + v * DG + tx * 4);
#pragma unroll
    for (int i = 0; i < 4; i++) {
        const int sl = ty * 4 + i;
        if (base + sl < count) {
            float4 o;
            o.x = acc[i][0] + bq4.x; o.y = acc[i][1] + bq4.y;
            o.z = acc[i][2] + bq4.z; o.w = acc[i][3] + bq4.w;
            *(float4*)(qsel + ((size_t)(v * UCAP + base + sl)) * DG + tx * 4) = o;
        }
    }
}

// ---------------------------------------------------------------------------
// resolve_k: exact scores for unresolved groups, iterating the ulist only.
// grid (UCAP/256, 16 v).
// ---------------------------------------------------------------------------
__global__ __launch_bounds__(256)
void resolve_k(const float* __restrict__ qsel, const float* __restrict__ cbk,
               const uint32_t* __restrict__ cand, const int* __restrict__ ucnt,
               const int* __restrict__ ulist,
               int* __restrict__ idxOut, int* __restrict__ counts) {
    const int v = blockIdx.y;
    const int slot = blockIdx.x * 256 + threadIdx.x;
    if (slot >= min(ucnt[v], UCAP)) return;
    const int row = ulist[v * UCAP + slot];
    const int g = row * VV + v;
    const int n = (-idxOut[g] - 1) & 15;
    const float* q = qsel + ((size_t)(v * UCAP + slot)) * DG;

    float q2 = 0.0f;
#pragma unroll
    for (int d = 0; d < DG; d += 4) {
        float4 y = *(const float4*)(q + d);
        q2 += y.x * y.x + y.y * y.y + y.z * y.z + y.w * y.w;
    }

    float bestS = -3.4e38f;
    int bestK = 0;
    for (int c = 0; c < n; c++) {
        const uint32_t wd = cand[g * 8 + c];
        const int k = (int)(wd & 511u);
        const uint32_t ub = wd >> 9;
        const float* cr = cbk + (((size_t)v * KK + k) << 6);
        float qc = 0.0f, c2 = 0.0f;
#pragma unroll
        for (int d = 0; d < DG; d += 4) {
            float4 xq = *(const float4*)(q + d);
            float4 yc = *(const float4*)(cr + d);
            qc += xq.x * yc.x + xq.y * yc.y + xq.z * yc.z + xq.w * yc.w;
            c2 += yc.x * yc.x + yc.y * yc.y + yc.z * yc.z + yc.w * yc.w;
        }
        const float dist = sqrtf(fmaxf(q2 + c2 - 2.0f * qc, 0.0f));
        const float s = gumbel_from_ubits(ub) - dist;
        if (s > bestS) { bestS = s; bestK = k; }   // ascending k: ties -> earliest
    }
    idxOut[g] = bestK;
    atomicAdd(&counts[v * KK + bestK], 1);
}

// ===========================================================================
// pmat: P[v][k][n] = sum_d codebooks[v][k][d] * Wout[n][v*64+d]  (+bout[n] @ v==0)
// ===========================================================================
__global__ __launch_bounds__(256)
void pmat_k(const float* __restrict__ cbk, const float* __restrict__ Wout,
            const float* __restrict__ bout, float* __restrict__ P) {
    __shared__ float Ct[64][65];
    __shared__ float Wt[128][65];
    const int v = blockIdx.z;
    const int k0 = blockIdx.y * 64;
    const int n0 = blockIdx.x * 128;
    const int tid = threadIdx.x;

    for (int i = tid; i < 64 * 16; i += 256) {
        int rr = i >> 4, dq = (i & 15) * 4;
        float4 c = *(const float4*)(cbk + (((size_t)v * KK + k0 + rr) << 6) + dq);
        Ct[rr][dq + 0] = c.x; Ct[rr][dq + 1] = c.y;
        Ct[rr][dq + 2] = c.z; Ct[rr][dq + 3] = c.w;
    }
    for (int i = tid; i < 128 * 16; i += 256) {
        int rr = i >> 4, dq = (i & 15) * 4;
        float4 wv = *(const float4*)(Wout + (size_t)(n0 + rr) * DD + v * DG + dq);
        Wt[rr][dq + 0] = wv.x; Wt[rr][dq + 1] = wv.y;
        Wt[rr][dq + 2] = wv.z; Wt[rr][dq + 3] = wv.w;
    }
    __syncthreads();

    const int ks = (tid >> 4) * 4;
    const int ns = (tid & 15) * 8;
    float acc[4][8];
#pragma unroll
    for (int i = 0; i < 4; i++)
#pragma unroll
        for (int j = 0; j < 8; j++) acc[i][j] = 0.0f;

#pragma unroll 8
    for (int d = 0; d < 64; d++) {
        float cv[4], wv[8];
#pragma unroll
        for (int i = 0; i < 4; i++) cv[i] = Ct[ks + i][d];
#pragma unroll
        for (int j = 0; j < 8; j++) wv[j] = Wt[ns + j][d];
#pragma unroll
        for (int i = 0; i < 4; i++)
#pragma unroll
            for (int j = 0; j < 8; j++)
                acc[i][j] = fmaf(cv[i], wv[j], acc[i][j]);
    }

#pragma unroll
    for (int i = 0; i < 4; i++) {
        float* prow = P + (((size_t)v * KK + k0 + ks + i) << 10) + n0 + ns;
        float4 o0, o1;
        float b0 = 0, b1 = 0, b2 = 0, b3 = 0, b4 = 0, b5 = 0, b6 = 0, b7 = 0;
        if (v == 0) {
            b0 = bout[n0 + ns + 0]; b1 = bout[n0 + ns + 1];
            b2 = bout[n0 + ns + 2]; b3 = bout[n0 + ns + 3];
            b4 = bout[n0 + ns + 4]; b5 = bout[n0 + ns + 5];
            b6 = bout[n0 + ns + 6]; b7 = bout[n0 + ns + 7];
        }
        o0.x = acc[i][0] + b0; o0.y = acc[i][1] + b1;
        o0.z = acc[i][2] + b2; o0.w = acc[i][3] + b3;
        o1.x = acc[i][4] + b4; o1.y = acc[i][5] + b5;
        o1.z = acc[i][6] + b6; o1.w = acc[i][7] + b7;
        *(float4*)(prow + 0) = o0;
        *(float4*)(prow + 4) = o1;
    }
}

// ---------------------------------------------------------------------------
// gather_sum: quantized[b,t] = sum_v P[v][idx_v]; also emits targets.
// ---------------------------------------------------------------------------
__global__ __launch_bounds__(128)
void gather_sum(const float* __restrict__ P, const int* __restrict__ idx,
                float* __restrict__ out) {
    __shared__ int sidx[VV];
    const int row = blockIdx.x;
    const int tid = threadIdx.x;
    if (tid < VV) sidx[tid] = idx[row * VV + tid];
    __syncthreads();

    const int n = tid * 8;
    float4 a0 = make_float4(0.f, 0.f, 0.f, 0.f);
    float4 a1 = make_float4(0.f, 0.f, 0.f, 0.f);
#pragma unroll
    for (int v = 0; v < VV; v++) {
        const float* p = P + ((((size_t)v << 9) + sidx[v]) << 10) + n;
        float4 x = *(const float4*)(p + 0);
        float4 y = *(const float4*)(p + 4);
        a0.x += x.x; a0.y += x.y; a0.z += x.z; a0.w += x.w;
        a1.x += y.x; a1.y += y.y; a1.z += y.z; a1.w += y.w;
    }
    float* o = out + (size_t)row * DD + n;
    *(float4*)(o + 0) = a0;
    *(float4*)(o + 4) = a1;

    if (tid == 0) {
        int s = 0;
#pragma unroll
        for (int v = 0; v < VV; v++) s += sidx[v] * (v * KK);
        out[OUT_TARGETS + row] = (float)s;
    }
}

// ---------------------------------------------------------------------------
// Small kernels
// ---------------------------------------------------------------------------
__global__ void zero_counts_k(int* __restrict__ counts, int* __restrict__ ucnt) {
    int i = blockIdx.x * blockDim.x + threadIdx.x;
    if (i < VV * KK) counts[i] = 0;
    if (i < VV) ucnt[i] = 0;
}

__global__ void loss_k(const int* __restrict__ counts, float* __restrict__ out) {
    __shared__ float ent_s[VV];
    const int tid = threadIdx.x, lane = tid & 31, w = tid >> 5;
    if (w < VV) {
        float tot = 0.0f;
        for (int kk = lane; kk < KK; kk += 32) tot += (float)counts[w * KK + kk];
#pragma unroll
        for (int o = 16; o; o >>= 1) tot += __shfl_xor_sync(0xffffffffu, tot, o);
        float inv = 1.0f / tot;
        float pl = 0.0f;
        for (int kk = lane; kk < KK; kk += 32) {
            float p = (float)counts[w * KK + kk] * inv;
            pl += p * logf(p + 1e-8f);
        }
#pragma unroll
        for (int o = 16; o; o >>= 1) pl += __shfl_xor_sync(0xffffffffu, pl, o);
        if (lane == 0) ent_s[w] = -pl;
    }
    __syncthreads();
    if (tid == 0) {
        float lk = logf(512.0f);
        float acc = 0.0f;
#pragma unroll
        for (int v = 0; v < VV; v++) acc += ent_s[v] / lk;
        float diversity = -(acc / (float)VV);
        out[OUT_LOSS] = 0.1f * diversity;
    }
}

// ---------------------------------------------------------------------------
// Launch
// ---------------------------------------------------------------------------
extern "C" void kernel_launch(void* const* d_in, const int* in_sizes, int n_in,
                              void* d_out, int out_size) {
    const float* features  = (const float*)d_in[0];
    const float* codebooks = (const float*)d_in[1];
    const float* Wq        = (const float*)d_in[2];
    const float* bq        = (const float*)d_in[3];
    const float* Wout      = (const float*)d_in[4];
    const float* bout      = (const float*)d_in[5];
    float* out = (float*)d_out;

    float* Pb;  cudaGetSymbolAddress((void**)&Pb,  g_P);
    int* idxP;  cudaGetSymbolAddress((void**)&idxP, g_idx);
    uint32_t* candP; cudaGetSymbolAddress((void**)&candP, g_cand);
    int* cntP;  cudaGetSymbolAddress((void**)&cntP, g_counts);
    float* dP;  cudaGetSymbolAddress((void**)&dP,  g_delta);
    int* ucP;   cudaGetSymbolAddress((void**)&ucP, g_ucnt);
    int* ulP;   cudaGetSymbolAddress((void**)&ulP, g_ulist);
    float* qsP; cudaGetSymbolAddress((void**)&qsP, g_qsel);

    static cudaStream_t sB = nullptr;
    static cudaEvent_t evF = nullptr, evJ = nullptr;
    if (sB == nullptr) {
        cudaStreamCreateWithFlags(&sB, cudaStreamNonBlocking);
        cudaEventCreateWithFlags(&evF, cudaEventDisableTiming);
        cudaEventCreateWithFlags(&evJ, cudaEventDisableTiming);
    }

    // fork: pmat (independent of the main chain until gather_sum)
    cudaEventRecord(evF, 0);
    cudaStreamWaitEvent(sB, evF, 0);
    pmat_k<<<dim3(8, 8, VV), 256, 0, sB>>>(codebooks, Wout, bout, Pb);
    cudaEventRecord(evJ, sB);

    // main chain
    zero_counts_k<<<16, 512>>>(cntP, ucP);
    delta_k<<<VV, 512>>>(codebooks, dP);
    rng_k<<<VV * TT, 256>>>(dP, idxP, candP, cntP, ucP, ulP);
    qproj_k<<<dim3(UCAP / 64, VV), 256>>>(features, Wq, bq, ucP, ulP, qsP);
    resolve_k<<<dim3(UCAP / 256, VV), 256>>>(qsP, codebooks, candP, ucP, ulP,
                                             idxP, cntP);
    cudaStreamWaitEvent(0, evJ, 0);
    gather_sum<<<MROWS, 128>>>(Pb, idxP, out);
    loss_k<<<1, 512>>>(cntP, out);
}

// round 11
// speedup vs baseline: 1.9801x; 1.0386x over previous
#include <cuda_runtime.h>
#include <cstdint>

// ---------------------------------------------------------------------------
// GumbelVectorQuantizer forward, GB300.
// B=8, T=2048, D=1024, V=16, K=512, d=64.
// ---------------------------------------------------------------------------

#define BB   8
#define TT   2048
#define DD   1024
#define VV   16
#define KK   512
#define DG   64
#define MROWS (BB * TT)          // 16384
#define NGRP  (MROWS * VV)       // 262144
#define UCAP  4096               // per-v unresolved-slot capacity

#define OUT_QUANT   0
#define OUT_TARGETS (MROWS * DD)            // 16777216
#define OUT_LOSS    (MROWS * DD + MROWS)    // 16793600

// Scratch (device globals: allocation-free contract)
__device__ float    g_P[VV * KK * DD];     // P[v][k][:] = codebooks[v][k] @ Wout_v^T (+bout at v=0)
__device__ int      g_idx[NGRP];           // final idx, or -(1+(slot<<4)+n) marker
__device__ uint32_t g_cand[NGRP * 8];      // packed (ubits<<9)|k per candidate
__device__ int      g_counts[VV * KK];     // codebook usage counts
__device__ float    g_delta[VV];           // per-group safe score window
__device__ int      g_ucnt[VV];            // unresolved count per v
__device__ int      g_ulist[VV * UCAP];    // unresolved row ids per v
__device__ float    g_qsel[VV * UCAP * DG];// q slices for unresolved groups
__device__ int      g_fixcnt;              // #rows needing recompute
__device__ int      g_fixrows[NGRP];       // rows needing recompute (dups ok)

// ---------------------------------------------------------------------------
// Threefry2x32, JAX partitionable path, key = (0, 42). Bit-identical.
// ---------------------------------------------------------------------------
__device__ __forceinline__ uint32_t rotl32(uint32_t x, int r) {
    return __funnelshift_l(x, x, r);
}

#define TFR(r)            { x0 += x1; x1 = rotl32(x1, (r)) ^ x0; }
#define TFINJR(ka, kb, r) { x1 += (kb); x0 = x0 + (ka) + x1; \
                            x1 = rotl32(x1, (r)) ^ x0; }

__device__ __forceinline__ uint32_t tf_bits(uint32_t i) {
    const uint32_t KS1 = 42u;
    const uint32_t KS2 = 0x1BD11BDAu ^ 42u;
    uint32_t x1 = i + KS1;
    uint32_t x0 = x1;                          // round 1 with x0 = 0
    x1 = rotl32(x1, 13) ^ x0;
    TFR(15); TFR(26); TFR(6);
    TFINJR(KS1, KS2 + 1u, 17); TFR(29); TFR(16); TFR(24);
    TFINJR(KS2, 2u, 13);       TFR(15); TFR(26); TFR(6);
    TFINJR(0u, KS1 + 3u, 17);  TFR(29); TFR(16); TFR(24);
    TFINJR(KS1, KS2 + 4u, 13); TFR(15); TFR(26); TFR(6);
    x0 += KS2;
    x1 += 5u;
    return x0 ^ x1;
}

__device__ __forceinline__ float gumbel_from_ubits(uint32_t ub) {
    float u = __uint_as_float(0x3f800000u | ub) - 1.0f;
    return -logf(-logf(u + 1e-8f) + 1e-8f);
}

// ---------------------------------------------------------------------------
// delta_k: per-v safe window  Delta_v = 2*max_k ||c_k|| + margin
// ---------------------------------------------------------------------------
__global__ void delta_k(const float* __restrict__ cbk, float* __restrict__ gd) {
    __shared__ float red[16];
    const int v = blockIdx.x;
    const int k = threadIdx.x;
    const int lane = k & 31, w = k >> 5;
    const float* crow = cbk + ((size_t)(v * KK + k)) * DG;
    float s = 0.0f;
#pragma unroll
    for (int d = 0; d < DG; d += 4) {
        float4 c = *(const float4*)(crow + d);
        s += c.x * c.x + c.y * c.y + c.z * c.z + c.w * c.w;
    }
#pragma unroll
    for (int o = 16; o; o >>= 1) s = fmaxf(s, __shfl_xor_sync(0xffffffffu, s, o));
    if (lane == 0) red[w] = s;
    __syncthreads();
    if (k == 0) {
        float m = 0.0f;
#pragma unroll
        for (int i = 0; i < 16; i++) m = fmaxf(m, red[i]);
        gd[v] = 2.0f * sqrtf(m) + 0.005f;
    }
}

// ---------------------------------------------------------------------------
// rng_k: threefry + integer max + threshold + candidate collection.
// ---------------------------------------------------------------------------
__global__ __launch_bounds__(256)
void rng_k(const float* __restrict__ gdelta, int* __restrict__ idxOut,
           uint32_t* __restrict__ candOut, int* __restrict__ counts,
           int* __restrict__ ucnt, int* __restrict__ ulist) {
    const int v = blockIdx.x >> 11;
    const int t = blockIdx.x & 2047;
    const int b = threadIdx.x >> 5;
    const int lane = threadIdx.x & 31;

    const uint32_t base = (uint32_t)t * 8192u + (uint32_t)v * 512u +
                          ((uint32_t)b << 24) + (uint32_t)lane;
    uint32_t r[16];
    uint32_t m = 0u;
#pragma unroll
    for (int j = 0; j < 16; j++) {
        r[j] = tf_bits(base + 32u * j);
        m = max(m, r[j]);
    }
#pragma unroll
    for (int o = 16; o; o >>= 1) m = max(m, __shfl_xor_sync(0xffffffffu, m, o));

    const float gmax = gumbel_from_ubits(m >> 9);
    const float glo = gmax - gdelta[v];
    const float ulo = expf(-(expf(-glo) - 1e-8f)) - 1e-8f;
    const int it = (int)floorf(ulo * 8388608.0f) - 16;
    const uint32_t thr = ((uint32_t)max(it, 0)) << 9;

    const int row = b * TT + t;
    const int group = row * VV + v;
    int cnt = 0;
    int firstK = 0;
#pragma unroll
    for (int j = 0; j < 16; j++) {
        unsigned mask = __ballot_sync(0xffffffffu, r[j] >= thr);
        while (mask) {
            const int src = __ffs(mask) - 1;
            mask &= mask - 1;
            const int kc = 32 * j + src;
            const uint32_t ub = __shfl_sync(0xffffffffu, r[j], src) >> 9;
            if (lane == 0 && cnt < 8)
                candOut[group * 8 + cnt] = (ub << 9) | (uint32_t)kc;
            if (cnt == 0) firstK = kc;
            cnt++;
        }
    }
    if (lane == 0) {
        if (cnt == 1) {
            idxOut[group] = firstK;
            atomicAdd(&counts[v * KK + firstK], 1);
        } else {
            int slot = atomicAdd(&ucnt[v], 1);
            slot = min(slot, UCAP - 1);   // statistically unreachable guard
            ulist[v * UCAP + slot] = row;
            idxOut[group] = -(1 + (slot << 4) + min(cnt, 8));
        }
    }
}

// ---------------------------------------------------------------------------
// qproj_k: selective q projection for unresolved groups.
// ---------------------------------------------------------------------------
__global__ __launch_bounds__(256)
void qproj_k(const float* __restrict__ feats, const float* __restrict__ Wq,
             const float* __restrict__ bq, const int* __restrict__ ucnt,
             const int* __restrict__ ulist, float* __restrict__ qsel) {
    __shared__ float As[16][68];
    __shared__ float Ws[16][68];
    __shared__ int rows[64];

    const int v = blockIdx.y;
    const int chunk = blockIdx.x;
    const int count = min(ucnt[v], UCAP);
    const int base = chunk * 64;
    if (base >= count) return;

    const int tid = threadIdx.x;
    if (tid < 64) rows[tid] = ulist[v * UCAP + min(base + tid, count - 1)];
    __syncthreads();

    const int lrow = tid >> 2;
    const int lcol = (tid & 3) * 4;
    const float* Ag = feats + (size_t)rows[lrow] * DD + lcol;
    const float* Wg = Wq + (size_t)(v * DG + lrow) * DD + lcol;

    const int tx = tid & 15;
    const int ty = tid >> 4;
    float acc[4][4];
#pragma unroll
    for (int i = 0; i < 4; i++)
#pragma unroll
        for (int j = 0; j < 4; j++) acc[i][j] = 0.0f;

    for (int k0 = 0; k0 < DD; k0 += 16) {
        float4 a = *(const float4*)(Ag + k0);
        float4 w = *(const float4*)(Wg + k0);
        __syncthreads();
        As[lcol + 0][lrow] = a.x; As[lcol + 1][lrow] = a.y;
        As[lcol + 2][lrow] = a.z; As[lcol + 3][lrow] = a.w;
        Ws[lcol + 0][lrow] = w.x; Ws[lcol + 1][lrow] = w.y;
        Ws[lcol + 2][lrow] = w.z; Ws[lcol + 3][lrow] = w.w;
        __syncthreads();
#pragma unroll
        for (int kk = 0; kk < 16; kk++) {
            float4 rm = *(const float4*)&As[kk][ty * 4];
            float4 rn = *(const float4*)&Ws[kk][tx * 4];
            float m0 = rm.x, m1 = rm.y, m2 = rm.z, m3 = rm.w;
            float n0 = rn.x, n1 = rn.y, n2 = rn.z, n3 = rn.w;
            acc[0][0] = fmaf(m0, n0, acc[0][0]); acc[0][1] = fmaf(m0, n1, acc[0][1]);
            acc[0][2] = fmaf(m0, n2, acc[0][2]); acc[0][3] = fmaf(m0, n3, acc[0][3]);
            acc[1][0] = fmaf(m1, n0, acc[1][0]); acc[1][1] = fmaf(m1, n1, acc[1][1]);
            acc[1][2] = fmaf(m1, n2, acc[1][2]); acc[1][3] = fmaf(m1, n3, acc[1][3]);
            acc[2][0] = fmaf(m2, n0, acc[2][0]); acc[2][1] = fmaf(m2, n1, acc[2][1]);
            acc[2][2] = fmaf(m2, n2, acc[2][2]); acc[2][3] = fmaf(m2, n3, acc[2][3]);
            acc[3][0] = fmaf(m3, n0, acc[3][0]); acc[3][1] = fmaf(m3, n1, acc[3][1]);
            acc[3][2] = fmaf(m3, n2, acc[3][2]); acc[3][3] = fmaf(m3, n3, acc[3][3]);
        }
    }

    const float4 bq4 = *(const float4*)(bq + v * DG + tx * 4);
#pragma unroll
    for (int i = 0; i < 4; i++) {
        const int sl = ty * 4 + i;
        if (base + sl < count) {
            float4 o;
            o.x = acc[i][0] + bq4.x; o.y = acc[i][1] + bq4.y;
            o.z = acc[i][2] + bq4.z; o.w = acc[i][3] + bq4.w;
            *(float4*)(qsel + ((size_t)(v * UCAP + base + sl)) * DG + tx * 4) = o;
        }
    }
}

// ---------------------------------------------------------------------------
// resolve_k: exact scores for unresolved groups; appends rows whose winner
// differs from the provisional (first candidate) to the fix list.
// ---------------------------------------------------------------------------
__global__ __launch_bounds__(256)
void resolve_k(const float* __restrict__ qsel, const float* __restrict__ cbk,
               const uint32_t* __restrict__ cand, const int* __restrict__ ucnt,
               const int* __restrict__ ulist,
               int* __restrict__ idxOut, int* __restrict__ counts,
               int* __restrict__ fixcnt, int* __restrict__ fixrows) {
    const int v = blockIdx.y;
    const int slot = blockIdx.x * 256 + threadIdx.x;
    if (slot >= min(ucnt[v], UCAP)) return;
    const int row = ulist[v * UCAP + slot];
    const int g = row * VV + v;
    const int n = (-idxOut[g] - 1) & 15;
    const float* q = qsel + ((size_t)(v * UCAP + slot)) * DG;

    float q2 = 0.0f;
#pragma unroll
    for (int d = 0; d < DG; d += 4) {
        float4 y = *(const float4*)(q + d);
        q2 += y.x * y.x + y.y * y.y + y.z * y.z + y.w * y.w;
    }

    float bestS = -3.4e38f;
    int bestK = 0;
    const int firstK = (int)(cand[g * 8] & 511u);
    for (int c = 0; c < n; c++) {
        const uint32_t wd = cand[g * 8 + c];
        const int k = (int)(wd & 511u);
        const uint32_t ub = wd >> 9;
        const float* cr = cbk + (((size_t)v * KK + k) << 6);
        float qc = 0.0f, c2 = 0.0f;
#pragma unroll
        for (int d = 0; d < DG; d += 4) {
            float4 xq = *(const float4*)(q + d);
            float4 yc = *(const float4*)(cr + d);
            qc += xq.x * yc.x + xq.y * yc.y + xq.z * yc.z + xq.w * yc.w;
            c2 += yc.x * yc.x + yc.y * yc.y + yc.z * yc.z + yc.w * yc.w;
        }
        const float dist = sqrtf(fmaxf(q2 + c2 - 2.0f * qc, 0.0f));
        const float s = gumbel_from_ubits(ub) - dist;
        if (s > bestS) { bestS = s; bestK = k; }   // ascending k: ties -> earliest
    }
    idxOut[g] = bestK;
    atomicAdd(&counts[v * KK + bestK], 1);
    if (bestK != firstK) {
        int p = atomicAdd(fixcnt, 1);
        fixrows[p] = row;
    }
}

// ===========================================================================
// pmat: P[v][k][n] = sum_d codebooks[v][k][d] * Wout[n][v*64+d]  (+bout[n] @ v==0)
// ===========================================================================
__global__ __launch_bounds__(256)
void pmat_k(const float* __restrict__ cbk, const float* __restrict__ Wout,
            const float* __restrict__ bout, float* __restrict__ P) {
    __shared__ float Ct[64][65];
    __shared__ float Wt[128][65];
    const int v = blockIdx.z;
    const int k0 = blockIdx.y * 64;
    const int n0 = blockIdx.x * 128;
    const int tid = threadIdx.x;

    for (int i = tid; i < 64 * 16; i += 256) {
        int rr = i >> 4, dq = (i & 15) * 4;
        float4 c = *(const float4*)(cbk + (((size_t)v * KK + k0 + rr) << 6) + dq);
        Ct[rr][dq + 0] = c.x; Ct[rr][dq + 1] = c.y;
        Ct[rr][dq + 2] = c.z; Ct[rr][dq + 3] = c.w;
    }
    for (int i = tid; i < 128 * 16; i += 256) {
        int rr = i >> 4, dq = (i & 15) * 4;
        float4 wv = *(const float4*)(Wout + (size_t)(n0 + rr) * DD + v * DG + dq);
        Wt[rr][dq + 0] = wv.x; Wt[rr][dq + 1] = wv.y;
        Wt[rr][dq + 2] = wv.z; Wt[rr][dq + 3] = wv.w;
    }
    __syncthreads();

    const int ks = (tid >> 4) * 4;
    const int ns = (tid & 15) * 8;
    float acc[4][8];
#pragma unroll
    for (int i = 0; i < 4; i++)
#pragma unroll
        for (int j = 0; j < 8; j++) acc[i][j] = 0.0f;

#pragma unroll 8
    for (int d = 0; d < 64; d++) {
        float cv[4], wv[8];
#pragma unroll
        for (int i = 0; i < 4; i++) cv[i] = Ct[ks + i][d];
#pragma unroll
        for (int j = 0; j < 8; j++) wv[j] = Wt[ns + j][d];
#pragma unroll
        for (int i = 0; i < 4; i++)
#pragma unroll
            for (int j = 0; j < 8; j++)
                acc[i][j] = fmaf(cv[i], wv[j], acc[i][j]);
    }

#pragma unroll
    for (int i = 0; i < 4; i++) {
        float* prow = P + (((size_t)v * KK + k0 + ks + i) << 10) + n0 + ns;
        float4 o0, o1;
        float b0 = 0, b1 = 0, b2 = 0, b3 = 0, b4 = 0, b5 = 0, b6 = 0, b7 = 0;
        if (v == 0) {
            b0 = bout[n0 + ns + 0]; b1 = bout[n0 + ns + 1];
            b2 = bout[n0 + ns + 2]; b3 = bout[n0 + ns + 3];
            b4 = bout[n0 + ns + 4]; b5 = bout[n0 + ns + 5];
            b6 = bout[n0 + ns + 6]; b7 = bout[n0 + ns + 7];
        }
        o0.x = acc[i][0] + b0; o0.y = acc[i][1] + b1;
        o0.z = acc[i][2] + b2; o0.w = acc[i][3] + b3;
        o1.x = acc[i][4] + b4; o1.y = acc[i][5] + b5;
        o1.z = acc[i][6] + b6; o1.w = acc[i][7] + b7;
        *(float4*)(prow + 0) = o0;
        *(float4*)(prow + 4) = o1;
    }
}

// ---------------------------------------------------------------------------
// gather_prov: quantized[b,t] = sum_v P[v][k_v] using final idx where ready,
// else the first candidate (provisional). Rows whose provisional differs from
// final are recomputed by fixup_k. Also emits provisional targets.
// ---------------------------------------------------------------------------
__device__ __forceinline__ void gather_row(const float* __restrict__ P,
                                           const int* __restrict__ sidx,
                                           float* __restrict__ out,
                                           int row, int tid) {
    const int n = tid * 8;
    float4 a0 = make_float4(0.f, 0.f, 0.f, 0.f);
    float4 a1 = make_float4(0.f, 0.f, 0.f, 0.f);
#pragma unroll
    for (int v = 0; v < VV; v++) {
        const float* p = P + ((((size_t)v << 9) + sidx[v]) << 10) + n;
        float4 x = *(const float4*)(p + 0);
        float4 y = *(const float4*)(p + 4);
        a0.x += x.x; a0.y += x.y; a0.z += x.z; a0.w += x.w;
        a1.x += y.x; a1.y += y.y; a1.z += y.z; a1.w += y.w;
    }
    float* o = out + (size_t)row * DD + n;
    *(float4*)(o + 0) = a0;
    *(float4*)(o + 4) = a1;
    if (tid == 0) {
        int s = 0;
#pragma unroll
        for (int v = 0; v < VV; v++) s += sidx[v] * (v * KK);
        out[OUT_TARGETS + row] = (float)s;
    }
}

__global__ __launch_bounds__(128)
void gather_prov(const float* __restrict__ P, const int* __restrict__ idx,
                 const uint32_t* __restrict__ cand, float* __restrict__ out) {
    __shared__ int sidx[VV];
    const int row = blockIdx.x;
    const int tid = threadIdx.x;
    if (tid < VV) {
        const int g = row * VV + tid;
        const int m = idx[g];
        sidx[tid] = (m >= 0) ? m : (int)(cand[g * 8] & 511u);
    }
    __syncthreads();
    gather_row(P, sidx, out, row, tid);
}

__global__ __launch_bounds__(128)
void fixup_k(const float* __restrict__ P, const int* __restrict__ idx,
             const int* __restrict__ fixcnt, const int* __restrict__ fixrows,
             float* __restrict__ out) {
    __shared__ int sidx[VV];
    const int tid = threadIdx.x;
    const int cnt = *fixcnt;
    for (int e = blockIdx.x; e < cnt; e += gridDim.x) {
        const int row = fixrows[e];
        if (tid < VV) sidx[tid] = idx[row * VV + tid];   // all final now
        __syncthreads();
        gather_row(P, sidx, out, row, tid);
        __syncthreads();
    }
}

// ---------------------------------------------------------------------------
// Small kernels
// ---------------------------------------------------------------------------
__global__ void zero_counts_k(int* __restrict__ counts, int* __restrict__ ucnt,
                              int* __restrict__ fixcnt) {
    int i = blockIdx.x * blockDim.x + threadIdx.x;
    if (i < VV * KK) counts[i] = 0;
    if (i < VV) ucnt[i] = 0;
    if (i == 0) *fixcnt = 0;
}

__global__ void loss_k(const int* __restrict__ counts, float* __restrict__ out) {
    __shared__ float ent_s[VV];
    const int tid = threadIdx.x, lane = tid & 31, w = tid >> 5;
    if (w < VV) {
        float tot = 0.0f;
        for (int kk = lane; kk < KK; kk += 32) tot += (float)counts[w * KK + kk];
#pragma unroll
        for (int o = 16; o; o >>= 1) tot += __shfl_xor_sync(0xffffffffu, tot, o);
        float inv = 1.0f / tot;
        float pl = 0.0f;
        for (int kk = lane; kk < KK; kk += 32) {
            float p = (float)counts[w * KK + kk] * inv;
            pl += p * logf(p + 1e-8f);
        }
#pragma unroll
        for (int o = 16; o; o >>= 1) pl += __shfl_xor_sync(0xffffffffu, pl, o);
        if (lane == 0) ent_s[w] = -pl;
    }
    __syncthreads();
    if (tid == 0) {
        float lk = logf(512.0f);
        float acc = 0.0f;
#pragma unroll
        for (int v = 0; v < VV; v++) acc += ent_s[v] / lk;
        float diversity = -(acc / (float)VV);
        out[OUT_LOSS] = 0.1f * diversity;
    }
}

// ---------------------------------------------------------------------------
// Launch: two-stream graph.
// stream A: zero/delta -> rng -> qproj -> resolve -> loss -> (wait B) fixup
// stream B: pmat -> (wait rng) gather_prov
// ---------------------------------------------------------------------------
extern "C" void kernel_launch(void* const* d_in, const int* in_sizes, int n_in,
                              void* d_out, int out_size) {
    const float* features  = (const float*)d_in[0];
    const float* codebooks = (const float*)d_in[1];
    const float* Wq        = (const float*)d_in[2];
    const float* bq        = (const float*)d_in[3];
    const float* Wout      = (const float*)d_in[4];
    const float* bout      = (const float*)d_in[5];
    float* out = (float*)d_out;

    float* Pb;  cudaGetSymbolAddress((void**)&Pb,  g_P);
    int* idxP;  cudaGetSymbolAddress((void**)&idxP, g_idx);
    uint32_t* candP; cudaGetSymbolAddress((void**)&candP, g_cand);
    int* cntP;  cudaGetSymbolAddress((void**)&cntP, g_counts);
    float* dP;  cudaGetSymbolAddress((void**)&dP,  g_delta);
    int* ucP;   cudaGetSymbolAddress((void**)&ucP, g_ucnt);
    int* ulP;   cudaGetSymbolAddress((void**)&ulP, g_ulist);
    float* qsP; cudaGetSymbolAddress((void**)&qsP, g_qsel);
    int* fcP;   cudaGetSymbolAddress((void**)&fcP, g_fixcnt);
    int* frP;   cudaGetSymbolAddress((void**)&frP, g_fixrows);

    static cudaStream_t sB = nullptr;
    static cudaEvent_t evF = nullptr, evR = nullptr, evG = nullptr;
    if (sB == nullptr) {
        cudaStreamCreateWithFlags(&sB, cudaStreamNonBlocking);
        cudaEventCreateWithFlags(&evF, cudaEventDisableTiming);
        cudaEventCreateWithFlags(&evR, cudaEventDisableTiming);
        cudaEventCreateWithFlags(&evG, cudaEventDisableTiming);
    }

    // fork
    cudaEventRecord(evF, 0);
    cudaStreamWaitEvent(sB, evF, 0);
    pmat_k<<<dim3(8, 8, VV), 256, 0, sB>>>(codebooks, Wout, bout, Pb);

    // stream A: main chain
    zero_counts_k<<<16, 512>>>(cntP, ucP, fcP);
    delta_k<<<VV, 512>>>(codebooks, dP);
    rng_k<<<VV * TT, 256>>>(dP, idxP, candP, cntP, ucP, ulP);
    cudaEventRecord(evR, 0);

    // stream B: provisional gather (concurrent with qproj/resolve)
    cudaStreamWaitEvent(sB, evR, 0);
    gather_prov<<<MROWS, 128, 0, sB>>>(Pb, idxP, candP, out);
    cudaEventRecord(evG, sB);

    // stream A: resolve the ambiguous groups
    qproj_k<<<dim3(UCAP / 64, VV), 256>>>(features, Wq, bq, ucP, ulP, qsP);
    resolve_k<<<dim3(UCAP / 256, VV), 256>>>(qsP, codebooks, candP, ucP, ulP,
                                             idxP, cntP, fcP, frP);
    loss_k<<<1, 512>>>(cntP, out);

    // join: recompute rows whose provisional winner was wrong
    cudaStreamWaitEvent(0, evG, 0);
    fixup_k<<<2048, 128>>>(Pb, idxP, fcP, frP, out);
}